// round 5
// baseline (speedup 1.0000x reference)
#include <cuda_runtime.h>
#include <cuda_bf16.h>
#include <cstdint>
#include <cstddef>

#define S_LEN 2048
#define D_EMB 2048
#define NHEAD 16
#define HDIM 64
#define DVDIM 128
#define BATCH 2
#define MROWS (BATCH * S_LEN)   // 4096
#define NQKV 6144
#define WCOLS 8192

#define LAMBDA_INIT_F 0.78360576653162435f
#define ONE_MINUS_LI_F 0.21639423346837565f

// ---------------- scratch (device globals) -------------------------------
__device__ float g_QKV[(size_t)MROWS * NQKV];
__device__ float g_A[(size_t)MROWS * D_EMB];
__device__ float g_lam;

__device__ __nv_bfloat16 g_xhi[(size_t)MROWS * D_EMB];
__device__ __nv_bfloat16 g_xlo[(size_t)MROWS * D_EMB];
__device__ __nv_bfloat16 g_whi[(size_t)D_EMB * WCOLS];   // [K, Wq|Wk|Wv|Wo]
__device__ __nv_bfloat16 g_wlo[(size_t)D_EMB * WCOLS];
__device__ __nv_bfloat16 g_ahi[(size_t)MROWS * D_EMB];
__device__ __nv_bfloat16 g_alo[(size_t)MROWS * D_EMB];

__device__ __nv_bfloat16 g_Qhi[(size_t)MROWS * D_EMB];
__device__ __nv_bfloat16 g_Qlo[(size_t)MROWS * D_EMB];
__device__ __nv_bfloat16 g_Khi[(size_t)MROWS * D_EMB];
__device__ __nv_bfloat16 g_Klo[(size_t)MROWS * D_EMB];
__device__ __nv_bfloat16 g_Vhi[(size_t)MROWS * D_EMB];
__device__ __nv_bfloat16 g_Vlo[(size_t)MROWS * D_EMB];

// ---------------- common PTX helpers --------------------------------------
__device__ __forceinline__ uint32_t smem_u32(const void* p) {
    return (uint32_t)__cvta_generic_to_shared(p);
}
__device__ __forceinline__ void cp16(uint32_t s, const void* g) {
    asm volatile("cp.async.ca.shared.global [%0], [%1], 16;" :: "r"(s), "l"(g));
}
__device__ __forceinline__ void cp16cg(uint32_t s, const void* g) {
    asm volatile("cp.async.cg.shared.global [%0], [%1], 16;" :: "r"(s), "l"(g));
}
__device__ __forceinline__ void ldmx4(uint32_t r[4], uint32_t addr) {
    asm volatile("ldmatrix.sync.aligned.m8n8.x4.shared.b16 {%0,%1,%2,%3}, [%4];"
        : "=r"(r[0]), "=r"(r[1]), "=r"(r[2]), "=r"(r[3]) : "r"(addr));
}
__device__ __forceinline__ void ldmx2t(uint32_t r[2], uint32_t addr) {
    asm volatile("ldmatrix.sync.aligned.m8n8.x2.trans.shared.b16 {%0,%1}, [%2];"
        : "=r"(r[0]), "=r"(r[1]) : "r"(addr));
}
__device__ __forceinline__ void mma_bf16(float c[4], const uint32_t a[4], const uint32_t b[2]) {
    asm volatile("mma.sync.aligned.m16n8k16.row.col.f32.bf16.bf16.f32 "
        "{%0,%1,%2,%3}, {%4,%5,%6,%7}, {%8,%9}, {%0,%1,%2,%3};"
        : "+f"(c[0]), "+f"(c[1]), "+f"(c[2]), "+f"(c[3])
        : "r"(a[0]), "r"(a[1]), "r"(a[2]), "r"(a[3]), "r"(b[0]), "r"(b[1]));
}
__device__ __forceinline__ uint32_t pack_bf16(float lo, float hi) {
    uint32_t r;
    asm("cvt.rn.bf16x2.f32 %0, %1, %2;" : "=r"(r) : "f"(hi), "f"(lo));
    return r;
}
__device__ __forceinline__ float fexp(float x) {
    float t = fmaxf(x, -60.0f) * 1.44269504088896340736f;
    float fi = floorf(t);
    float f = t - fi;
    float p = 1.53964252399628e-4f;
    p = p * f + 1.33336498402e-3f;
    p = p * f + 9.61817668305e-3f;
    p = p * f + 5.55041086648e-2f;
    p = p * f + 2.40226506959101e-1f;
    p = p * f + 6.93147180559945e-1f;
    p = p * f + 1.0f;
    return __int_as_float(__float_as_int(p) + (((int)fi) << 23));
}

// =================== fp32 -> (bf16 hi, bf16 lo) split ====================
__global__ void split_kernel(const float* __restrict__ in,
                             __nv_bfloat16* __restrict__ hi,
                             __nv_bfloat16* __restrict__ lo, int n4)
{
    int i = blockIdx.x * blockDim.x + threadIdx.x;
    if (i >= n4) return;
    float4 v = ((const float4*)in)[i];
    __nv_bfloat16 hx = __float2bfloat16(v.x);
    __nv_bfloat16 hy = __float2bfloat16(v.y);
    __nv_bfloat16 hz = __float2bfloat16(v.z);
    __nv_bfloat16 hw = __float2bfloat16(v.w);
    __nv_bfloat16 lx = __float2bfloat16(v.x - __bfloat162float(hx));
    __nv_bfloat16 ly = __float2bfloat16(v.y - __bfloat162float(hy));
    __nv_bfloat16 lz = __float2bfloat16(v.z - __bfloat162float(hz));
    __nv_bfloat16 lw = __float2bfloat16(v.w - __bfloat162float(hw));
    __nv_bfloat162* H = (__nv_bfloat162*)hi;
    __nv_bfloat162* L = (__nv_bfloat162*)lo;
    H[2 * i]     = __halves2bfloat162(hx, hy);
    H[2 * i + 1] = __halves2bfloat162(hz, hw);
    L[2 * i]     = __halves2bfloat162(lx, ly);
    L[2 * i + 1] = __halves2bfloat162(lz, lw);
}

// ===== W [2048,2048] -> packed [2048, 8192] at column offset + split =====
__global__ void wsplit_kernel(const float* __restrict__ in,
                              __nv_bfloat16* __restrict__ hi,
                              __nv_bfloat16* __restrict__ lo, int colOff)
{
    int i = blockIdx.x * blockDim.x + threadIdx.x;   // over 2048*2048/4
    if (i >= (D_EMB * D_EMB) / 4) return;
    int r = i >> 9;
    int c4 = (i & 511) << 2;
    float4 v = ((const float4*)in)[i];
    __nv_bfloat16 hx = __float2bfloat16(v.x);
    __nv_bfloat16 hy = __float2bfloat16(v.y);
    __nv_bfloat16 hz = __float2bfloat16(v.z);
    __nv_bfloat16 hw = __float2bfloat16(v.w);
    size_t o = (size_t)r * WCOLS + colOff + c4;
    ((__nv_bfloat162*)&hi[o])[0] = __halves2bfloat162(hx, hy);
    ((__nv_bfloat162*)&hi[o])[1] = __halves2bfloat162(hz, hw);
    ((__nv_bfloat162*)&lo[o])[0] = __halves2bfloat162(
        __float2bfloat16(v.x - __bfloat162float(hx)),
        __float2bfloat16(v.y - __bfloat162float(hy)));
    ((__nv_bfloat162*)&lo[o])[1] = __halves2bfloat162(
        __float2bfloat16(v.z - __bfloat162float(hz)),
        __float2bfloat16(v.w - __bfloat162float(hw)));
}

// =================== tensor-core GEMM (bf16 x3 split) ====================
// C[M,N] = A[M,K] * B[K,N]. 512 threads, 128x128 tile, BK=32, 3 stages.
#define GBK 32
#define GA_PITCH 80
#define GB_PITCH 272
#define GOFF_AL (128 * GA_PITCH)             // 10240
#define GOFF_BH (2 * 128 * GA_PITCH)         // 20480
#define GOFF_BL (GOFF_BH + GBK * GB_PITCH)   // 29184
#define GSTAGE (GOFF_BL + GBK * GB_PITCH)    // 37888
#define G_SMEM (3 * GSTAGE)                  // 113664

__global__ __launch_bounds__(512, 1)
void gemm_bf16x3(const __nv_bfloat16* __restrict__ Ahi, const __nv_bfloat16* __restrict__ Alo,
                 const __nv_bfloat16* __restrict__ Bhi, const __nv_bfloat16* __restrict__ Blo,
                 float* __restrict__ C, int M, int N, int K, int ldb, int ldc)
{
    extern __shared__ __align__(16) uint8_t gsm[];
    const uint32_t sbase = smem_u32(gsm);
    const int tid = threadIdx.x;
    const int lane = tid & 31;
    const int wid = tid >> 5;
    const int m0 = blockIdx.y * 128;
    const int n0 = blockIdx.x * 128;

    const int wm = wid & 7;      // 8 m-tiles of 16 rows
    const int wn = wid >> 3;     // 2 n-slabs of 64 cols

    const int KT = K / GBK;      // 64

    auto load_stage = [&](int t) {
        uint32_t st = sbase + (t % 3) * GSTAGE;
        int k0 = t * GBK;
#pragma unroll
        for (int j = 0; j < 4; j++) {
            int cid = tid + 512 * j;
            if (cid < 1024) {
                int hl = (cid >> 9) & 1;
                int sub = cid & 511;
                int row = sub >> 2;
                int ch = sub & 3;
                const __nv_bfloat16* src = (hl ? Alo : Ahi)
                    + (size_t)(m0 + row) * K + k0 + ch * 8;
                cp16cg(st + (hl ? GOFF_AL : 0) + row * GA_PITCH + ch * 16, src);
            } else {
                int c2 = cid - 1024;
                int hl = (c2 >> 9) & 1;
                int sub = c2 & 511;
                int row = sub >> 4;
                int ch = sub & 15;
                const __nv_bfloat16* src = (hl ? Blo : Bhi)
                    + (size_t)(k0 + row) * ldb + n0 + ch * 8;
                cp16cg(st + (hl ? GOFF_BL : GOFF_BH) + row * GB_PITCH + ch * 16, src);
            }
        }
        asm volatile("cp.async.commit_group;");
    };

    load_stage(0);
    load_stage(1);
    load_stage(2);

    float acc[8][4];
#pragma unroll
    for (int i = 0; i < 8; i++)
#pragma unroll
        for (int j = 0; j < 4; j++) acc[i][j] = 0.f;

    // ldmatrix addresses
    const int ar = wm * 16 + (lane & 7) + ((lane >> 3) & 1) * 8;
    const uint32_t acolb = ((lane >> 4) & 1) * 16;
    const uint32_t aoff = (uint32_t)ar * GA_PITCH + acolb;
    const uint32_t boff = (uint32_t)(lane & 15) * GB_PITCH + (uint32_t)wn * 128;

    for (int t = 0; t < KT; t++) {
        int rem = KT - 1 - t;
        if (rem >= 2)      asm volatile("cp.async.wait_group 2;");
        else if (rem == 1) asm volatile("cp.async.wait_group 1;");
        else               asm volatile("cp.async.wait_group 0;");
        __syncthreads();

        uint32_t st = sbase + (t % 3) * GSTAGE;
#pragma unroll
        for (int kk = 0; kk < 2; kk++) {
            uint32_t ah[4], al[4];
            ldmx4(ah, st + aoff + kk * 32);
            ldmx4(al, st + GOFF_AL + aoff + kk * 32);
            uint32_t bbase = st + boff + (uint32_t)kk * 16 * GB_PITCH;
#pragma unroll
            for (int nt = 0; nt < 8; nt++) {
                uint32_t bh[2], bl[2];
                ldmx2t(bh, bbase + GOFF_BH + nt * 16);
                ldmx2t(bl, bbase + GOFF_BL + nt * 16);
                mma_bf16(acc[nt], ah, bh);
                mma_bf16(acc[nt], al, bh);
                mma_bf16(acc[nt], ah, bl);
            }
        }
        __syncthreads();
        if (t + 3 < KT) load_stage(t + 3);
    }

    // epilogue
    const int gid = lane >> 2, tig = lane & 3;
    const int row = m0 + wm * 16 + gid;
#pragma unroll
    for (int nt = 0; nt < 8; nt++) {
        int col = n0 + wn * 64 + nt * 8 + 2 * tig;
        *(float2*)&C[(size_t)row * ldc + col] = make_float2(acc[nt][0], acc[nt][1]);
        *(float2*)&C[(size_t)(row + 8) * ldc + col] = make_float2(acc[nt][2], acc[nt][3]);
    }
}

// ---------------- RoPE + bf16 hi/lo split (Q,K from fused QKV) -----------
__global__ void rope_split_kernel(const float* __restrict__ QKV,
                                  __nv_bfloat16* __restrict__ Qhi, __nv_bfloat16* __restrict__ Qlo,
                                  __nv_bfloat16* __restrict__ Khi, __nv_bfloat16* __restrict__ Klo)
{
    const long total = (long)MROWS * (D_EMB / 2);
    const float LN1E4_OVER_32 = 9.210340371976184f / 32.0f;
    for (long p = (long)blockIdx.x * blockDim.x + threadIdx.x; p < total;
         p += (long)gridDim.x * blockDim.x) {
        int pcol = (int)(p & (D_EMB / 2 - 1));
        long row = p >> 10;
        int s = (int)(row & (S_LEN - 1));
        int j = pcol & 31;
        float inv = expf(-(float)j * LN1E4_OVER_32);
        float ang = (float)s * inv;
        float sn, cs;
        sincosf(ang, &sn, &cs);
        size_t idxq = (size_t)row * NQKV + 2 * pcol;
        size_t idxk = idxq + D_EMB;
        size_t pi = (size_t)row * (D_EMB / 2) + pcol;

        float q0 = QKV[idxq], q1 = QKV[idxq + 1];
        float rq0 = q0 * cs - q1 * sn;
        float rq1 = q1 * cs + q0 * sn;
        __nv_bfloat16 qh0 = __float2bfloat16(rq0);
        __nv_bfloat16 qh1 = __float2bfloat16(rq1);
        ((__nv_bfloat162*)Qhi)[pi] = __halves2bfloat162(qh0, qh1);
        ((__nv_bfloat162*)Qlo)[pi] = __halves2bfloat162(
            __float2bfloat16(rq0 - __bfloat162float(qh0)),
            __float2bfloat16(rq1 - __bfloat162float(qh1)));

        float k0 = QKV[idxk], k1 = QKV[idxk + 1];
        float rk0 = k0 * cs - k1 * sn;
        float rk1 = k1 * cs + k0 * sn;
        __nv_bfloat16 kh0 = __float2bfloat16(rk0);
        __nv_bfloat16 kh1 = __float2bfloat16(rk1);
        ((__nv_bfloat162*)Khi)[pi] = __halves2bfloat162(kh0, kh1);
        ((__nv_bfloat162*)Klo)[pi] = __halves2bfloat162(
            __float2bfloat16(rk0 - __bfloat162float(kh0)),
            __float2bfloat16(rk1 - __bfloat162float(kh1)));
    }
}

// ---------------- V split (from fused QKV, offset 4096, stride 6144) -----
__global__ void vsplit_kernel(const float* __restrict__ QKV,
                              __nv_bfloat16* __restrict__ hi,
                              __nv_bfloat16* __restrict__ lo)
{
    int i = blockIdx.x * blockDim.x + threadIdx.x;
    if (i >= (MROWS * D_EMB) / 4) return;
    int r = i >> 9;
    int c4 = (i & 511) << 2;
    float4 v = *(const float4*)&QKV[(size_t)r * NQKV + 2 * D_EMB + c4];
    __nv_bfloat16 hx = __float2bfloat16(v.x);
    __nv_bfloat16 hy = __float2bfloat16(v.y);
    __nv_bfloat16 hz = __float2bfloat16(v.z);
    __nv_bfloat16 hw = __float2bfloat16(v.w);
    size_t o = (size_t)r * D_EMB + c4;
    ((__nv_bfloat162*)&hi[o])[0] = __halves2bfloat162(hx, hy);
    ((__nv_bfloat162*)&hi[o])[1] = __halves2bfloat162(hz, hw);
    ((__nv_bfloat162*)&lo[o])[0] = __halves2bfloat162(
        __float2bfloat16(v.x - __bfloat162float(hx)),
        __float2bfloat16(v.y - __bfloat162float(hy)));
    ((__nv_bfloat162*)&lo[o])[1] = __halves2bfloat162(
        __float2bfloat16(v.z - __bfloat162float(hz)),
        __float2bfloat16(v.w - __bfloat162float(hw)));
}

// ---------------- lambda scalar ------------------------------------------
__global__ void lam_kernel(const float* __restrict__ lq1, const float* __restrict__ lk1,
                           const float* __restrict__ lq2, const float* __restrict__ lk2)
{
    __shared__ float s1[64], s2[64];
    int t = threadIdx.x;
    s1[t] = lq1[t] * lk1[t];
    s2[t] = lq2[t] * lk2[t];
    __syncthreads();
    if (t == 0) {
        float d1 = 0.f, d2 = 0.f;
        for (int i = 0; i < 64; i++) { d1 += s1[i]; d2 += s2[i]; }
        g_lam = expf(d1) - expf(d2) + LAMBDA_INIT_F;
    }
}

// ================= MMA dual-branch flash attention ========================
#define PQB 144
#define PVB 272
#define QK_TILE (64 * PQB)
#define V_TILE  (64 * PVB)
#define OFF_SQ 0
#define OFF_SK (4 * QK_TILE)
#define OFF_SV (8 * QK_TILE)
#define FL_SMEM (OFF_SV + 2 * V_TILE)

__global__ __launch_bounds__(256, 1)
void flash_mma_kernel(const __nv_bfloat16* __restrict__ Qhi, const __nv_bfloat16* __restrict__ Qlo,
                      const __nv_bfloat16* __restrict__ Khi, const __nv_bfloat16* __restrict__ Klo,
                      const __nv_bfloat16* __restrict__ Vhi, const __nv_bfloat16* __restrict__ Vlo,
                      const float* __restrict__ lnw, const float* __restrict__ lnb,
                      float* __restrict__ Aout)
{
    extern __shared__ __align__(16) uint8_t smraw[];
    const uint32_t sbase = smem_u32(smraw);
    float* sOut = (float*)(smraw + OFF_SK);

    const int tid = threadIdx.x;
    const int lane = tid & 31;
    const int wid = tid >> 5;
    const int br = wid >> 2;
    const int rbase = (wid & 3) * 16;
    const int g = lane >> 2;
    const int tg = lane & 3;

    const int qt = blockIdx.x;
    const int h = blockIdx.y;
    const int b = blockIdx.z;
    const int q0t = qt * 64;
    const size_t rowBase = (size_t)b * S_LEN;
    const int colH = h * 128;

#pragma unroll
    for (int it = 0; it < 8; it++) {
        int idx = tid + 256 * it;
        int ch = idx & 7, r = (idx >> 3) & 63, t = idx >> 9;
        const __nv_bfloat16* src = ((t & 1) ? Qlo : Qhi)
            + (rowBase + q0t + r) * D_EMB + colH + (t >> 1) * 64 + ch * 8;
        cp16(sbase + OFF_SQ + t * QK_TILE + r * PQB + ch * 16, src);
    }
    asm volatile("cp.async.commit_group;");
    asm volatile("cp.async.wait_group 0;");
    __syncthreads();

    uint32_t qh[4][4], ql[4][4];
    {
        uint32_t qoff = (uint32_t)(rbase + (lane & 15)) * PQB + ((lane >> 4) << 4);
        uint32_t bh_ = sbase + OFF_SQ + (br * 2) * QK_TILE;
#pragma unroll
        for (int s = 0; s < 4; s++) {
            ldmx4(qh[s], bh_ + qoff + s * 32);
            ldmx4(ql[s], bh_ + QK_TILE + qoff + s * 32);
        }
    }

    float o[16][4];
#pragma unroll
    for (int i = 0; i < 16; i++)
#pragma unroll
        for (int j = 0; j < 4; j++) o[i][j] = 0.f;
    float m_a = -1e30f, m_b = -1e30f, l_a = 0.f, l_b = 0.f;

    for (int kt = 0; kt <= qt; kt++) {
        __syncthreads();
#pragma unroll
        for (int it = 0; it < 8; it++) {
            int idx = tid + 256 * it;
            int ch = idx & 7, r = (idx >> 3) & 63, t = idx >> 9;
            const __nv_bfloat16* src = ((t & 1) ? Klo : Khi)
                + (rowBase + (size_t)kt * 64 + r) * D_EMB + colH + (t >> 1) * 64 + ch * 8;
            cp16(sbase + OFF_SK + t * QK_TILE + r * PQB + ch * 16, src);
        }
#pragma unroll
        for (int it = 0; it < 8; it++) {
            int idx = tid + 256 * it;
            int ch = idx & 15, r = (idx >> 4) & 63, t = idx >> 10;
            const __nv_bfloat16* src = (t ? Vlo : Vhi)
                + (rowBase + (size_t)kt * 64 + r) * D_EMB + colH + ch * 8;
            cp16(sbase + OFF_SV + t * V_TILE + r * PVB + ch * 16, src);
        }
        asm volatile("cp.async.commit_group;");
        asm volatile("cp.async.wait_group 0;");
        __syncthreads();

        float sc[8][4];
#pragma unroll
        for (int i = 0; i < 8; i++)
#pragma unroll
            for (int j = 0; j < 4; j++) sc[i][j] = 0.f;

        const uint32_t kbh = sbase + OFF_SK + (br * 2) * QK_TILE;
        const uint32_t koff = (uint32_t)(lane & 7) * PQB + ((lane >> 3) << 4);
#pragma unroll
        for (int nt = 0; nt < 8; nt++) {
            uint32_t a = koff + (uint32_t)nt * 8 * PQB;
            uint32_t kh0[4], kh1[4], kl0[4], kl1[4];
            ldmx4(kh0, kbh + a);
            ldmx4(kh1, kbh + a + 64);
            ldmx4(kl0, kbh + QK_TILE + a);
            ldmx4(kl1, kbh + QK_TILE + a + 64);
            mma_bf16(sc[nt], qh[0], &kh0[0]);
            mma_bf16(sc[nt], ql[0], &kh0[0]);
            mma_bf16(sc[nt], qh[0], &kl0[0]);
            mma_bf16(sc[nt], qh[1], &kh0[2]);
            mma_bf16(sc[nt], ql[1], &kh0[2]);
            mma_bf16(sc[nt], qh[1], &kl0[2]);
            mma_bf16(sc[nt], qh[2], &kh1[0]);
            mma_bf16(sc[nt], ql[2], &kh1[0]);
            mma_bf16(sc[nt], qh[2], &kl1[0]);
            mma_bf16(sc[nt], qh[3], &kh1[2]);
            mma_bf16(sc[nt], ql[3], &kh1[2]);
            mma_bf16(sc[nt], qh[3], &kl1[2]);
        }

        const bool diag = (kt == qt);
        float mxa = -1e30f, mxb = -1e30f;
#pragma unroll
        for (int nt = 0; nt < 8; nt++) {
            int c0 = nt * 8 + 2 * tg;
#pragma unroll
            for (int e = 0; e < 4; e++) {
                int row = rbase + g + ((e >> 1) << 3);
                int col = c0 + (e & 1);
                float v = sc[nt][e] * 0.125f;
                if (diag && col > row) v = -1e30f;
                sc[nt][e] = v;
            }
            mxa = fmaxf(mxa, fmaxf(sc[nt][0], sc[nt][1]));
            mxb = fmaxf(mxb, fmaxf(sc[nt][2], sc[nt][3]));
        }
        mxa = fmaxf(mxa, __shfl_xor_sync(0xffffffffu, mxa, 1));
        mxa = fmaxf(mxa, __shfl_xor_sync(0xffffffffu, mxa, 2));
        mxb = fmaxf(mxb, __shfl_xor_sync(0xffffffffu, mxb, 1));
        mxb = fmaxf(mxb, __shfl_xor_sync(0xffffffffu, mxb, 2));
        float mna = fmaxf(m_a, mxa), mnb = fmaxf(m_b, mxb);
        float alf_a = fexp(m_a - mna), alf_b = fexp(m_b - mnb);
        m_a = mna; m_b = mnb;

        float suma = 0.f, sumb = 0.f;
        uint32_t ph[4][4], pl[4][4];
#pragma unroll
        for (int s2 = 0; s2 < 4; s2++) {
#pragma unroll
            for (int hf = 0; hf < 2; hf++) {
                int nt = 2 * s2 + hf;
                float p0 = fexp(sc[nt][0] - m_a);
                float p1 = fexp(sc[nt][1] - m_a);
                float p2 = fexp(sc[nt][2] - m_b);
                float p3 = fexp(sc[nt][3] - m_b);
                suma += p0 + p1; sumb += p2 + p3;
                __nv_bfloat16 h0 = __float2bfloat16(p0);
                __nv_bfloat16 h1 = __float2bfloat16(p1);
                __nv_bfloat16 h2 = __float2bfloat16(p2);
                __nv_bfloat16 h3 = __float2bfloat16(p3);
                __nv_bfloat162 t01 = __halves2bfloat162(h0, h1);
                __nv_bfloat162 t23 = __halves2bfloat162(h2, h3);
                ph[s2][hf * 2 + 0] = *(uint32_t*)&t01;
                ph[s2][hf * 2 + 1] = *(uint32_t*)&t23;
                pl[s2][hf * 2 + 0] = pack_bf16(p0 - __bfloat162float(h0),
                                               p1 - __bfloat162float(h1));
                pl[s2][hf * 2 + 1] = pack_bf16(p2 - __bfloat162float(h2),
                                               p3 - __bfloat162float(h3));
            }
        }
        suma += __shfl_xor_sync(0xffffffffu, suma, 1);
        suma += __shfl_xor_sync(0xffffffffu, suma, 2);
        sumb += __shfl_xor_sync(0xffffffffu, sumb, 1);
        sumb += __shfl_xor_sync(0xffffffffu, sumb, 2);
        l_a = alf_a * l_a + suma;
        l_b = alf_b * l_b + sumb;

#pragma unroll
        for (int vt = 0; vt < 16; vt++) {
            o[vt][0] *= alf_a; o[vt][1] *= alf_a;
            o[vt][2] *= alf_b; o[vt][3] *= alf_b;
        }

        const uint32_t vb = sbase + OFF_SV;
        const uint32_t vrow = (uint32_t)(lane & 15) * PVB;
#pragma unroll
        for (int vt = 0; vt < 16; vt++) {
#pragma unroll
            for (int s2 = 0; s2 < 4; s2++) {
                uint32_t addr = (uint32_t)(s2 * 16) * PVB + vrow + vt * 16;
                uint32_t bh[2], bl[2];
                ldmx2t(bh, vb + addr);
                ldmx2t(bl, vb + V_TILE + addr);
                mma_bf16(o[vt], ph[s2], bh);
                mma_bf16(o[vt], pl[s2], bh);
                mma_bf16(o[vt], ph[s2], bl);
            }
        }
    }

    __syncthreads();
    float lam = g_lam;
    float ra = 1.0f / l_a, rb = 1.0f / l_b;

    if (br == 0) {
#pragma unroll
        for (int vt = 0; vt < 16; vt++) {
            int c = vt * 8 + 2 * tg;
            *(float2*)&sOut[(rbase + g) * 128 + c] = make_float2(o[vt][0] * ra, o[vt][1] * ra);
            *(float2*)&sOut[(rbase + g + 8) * 128 + c] = make_float2(o[vt][2] * rb, o[vt][3] * rb);
        }
    }
    __syncthreads();
    if (br == 1) {
#pragma unroll
        for (int vt = 0; vt < 16; vt++) {
            int c = vt * 8 + 2 * tg;
            float2* p0 = (float2*)&sOut[(rbase + g) * 128 + c];
            float2 v0 = *p0;
            v0.x -= lam * o[vt][0] * ra; v0.y -= lam * o[vt][1] * ra;
            *p0 = v0;
            float2* p1 = (float2*)&sOut[(rbase + g + 8) * 128 + c];
            float2 v1 = *p1;
            v1.x -= lam * o[vt][2] * rb; v1.y -= lam * o[vt][3] * rb;
            *p1 = v1;
        }
    }
    __syncthreads();

    {
        int r = tid >> 2;
        int q4 = tid & 3;
        float ss = 0.f;
#pragma unroll
        for (int u = 0; u < 32; u++) {
            float v = sOut[r * 128 + q4 * 32 + u];
            ss += v * v;
        }
        ss += __shfl_xor_sync(0xffffffffu, ss, 1);
        ss += __shfl_xor_sync(0xffffffffu, ss, 2);
        float rn = rsqrtf(ss * (1.0f / 128.0f) + 1e-8f);
        size_t outrow = (rowBase + q0t + r) * D_EMB + colH;
#pragma unroll
        for (int u = 0; u < 32; u++) {
            int e = q4 * 32 + u;
            Aout[outrow + e] = (sOut[r * 128 + e] * rn * lnw[e] + lnb[e]) * ONE_MINUS_LI_F;
        }
    }
}

// ---------------- launch ---------------------------------------------------
extern "C" void kernel_launch(void* const* d_in, const int* in_sizes, int n_in,
                              void* d_out, int out_size)
{
    (void)in_sizes; (void)n_in; (void)out_size;
    const float* x   = (const float*)d_in[0];
    const float* Wq  = (const float*)d_in[1];
    const float* Wk  = (const float*)d_in[2];
    const float* Wv  = (const float*)d_in[3];
    const float* Wo  = (const float*)d_in[4];
    const float* lq1 = (const float*)d_in[5];
    const float* lk1 = (const float*)d_in[6];
    const float* lq2 = (const float*)d_in[7];
    const float* lk2 = (const float*)d_in[8];
    const float* lnw = (const float*)d_in[9];
    const float* lnb = (const float*)d_in[10];
    float* out = (float*)d_out;

    float *qkv, *ap;
    cudaGetSymbolAddress((void**)&qkv, g_QKV);
    cudaGetSymbolAddress((void**)&ap, g_A);

    __nv_bfloat16 *xhi, *xlo, *whi, *wlo, *ahi, *alo;
    __nv_bfloat16 *qhi, *qlo, *khi, *klo, *vhi, *vlo;
    cudaGetSymbolAddress((void**)&xhi, g_xhi);
    cudaGetSymbolAddress((void**)&xlo, g_xlo);
    cudaGetSymbolAddress((void**)&whi, g_whi);
    cudaGetSymbolAddress((void**)&wlo, g_wlo);
    cudaGetSymbolAddress((void**)&ahi, g_ahi);
    cudaGetSymbolAddress((void**)&alo, g_alo);
    cudaGetSymbolAddress((void**)&qhi, g_Qhi);
    cudaGetSymbolAddress((void**)&qlo, g_Qlo);
    cudaGetSymbolAddress((void**)&khi, g_Khi);
    cudaGetSymbolAddress((void**)&klo, g_Klo);
    cudaGetSymbolAddress((void**)&vhi, g_Vhi);
    cudaGetSymbolAddress((void**)&vlo, g_Vlo);

    const int nx4 = (MROWS * D_EMB) / 4;
    const int nw4 = (D_EMB * D_EMB) / 4;

    split_kernel<<<(nx4 + 255) / 256, 256>>>(x, xhi, xlo, nx4);
    wsplit_kernel<<<(nw4 + 255) / 256, 256>>>(Wq, whi, wlo, 0);
    wsplit_kernel<<<(nw4 + 255) / 256, 256>>>(Wk, whi, wlo, 2048);
    wsplit_kernel<<<(nw4 + 255) / 256, 256>>>(Wv, whi, wlo, 4096);
    wsplit_kernel<<<(nw4 + 255) / 256, 256>>>(Wo, whi, wlo, 6144);

    cudaFuncSetAttribute(gemm_bf16x3, cudaFuncAttributeMaxDynamicSharedMemorySize, G_SMEM);

    // fused QKV projection: [4096, 2048] x [2048, 6144]
    dim3 gqkv(NQKV / 128, MROWS / 128);   // (48, 32)
    gemm_bf16x3<<<gqkv, 512, G_SMEM>>>(xhi, xlo, whi, wlo, qkv,
                                       MROWS, NQKV, D_EMB, WCOLS, NQKV);

    rope_split_kernel<<<2048, 256>>>(qkv, qhi, qlo, khi, klo);
    vsplit_kernel<<<(nx4 + 255) / 256, 256>>>(qkv, vhi, vlo);
    lam_kernel<<<1, 64>>>(lq1, lk1, lq2, lk2);

    cudaFuncSetAttribute(flash_mma_kernel, cudaFuncAttributeMaxDynamicSharedMemorySize, FL_SMEM);
    flash_mma_kernel<<<dim3(32, NHEAD, BATCH), 256, FL_SMEM>>>(
        qhi, qlo, khi, klo, vhi, vlo, lnw, lnb, ap);

    split_kernel<<<(nx4 + 255) / 256, 256>>>(ap, ahi, alo, nx4);

    // output projection: [4096, 2048] x [2048, 2048] (Wo at col 6144 of packed W)
    dim3 go(D_EMB / 128, MROWS / 128);    // (16, 32)
    gemm_bf16x3<<<go, 512, G_SMEM>>>(ahi, alo, whi + 6144, wlo + 6144, out,
                                     MROWS, D_EMB, D_EMB, WCOLS, D_EMB);
}

// round 6
// speedup vs baseline: 1.1114x; 1.1114x over previous
#include <cuda_runtime.h>
#include <cuda_bf16.h>
#include <cstdint>
#include <cstddef>

#define S_LEN 2048
#define D_EMB 2048
#define NHEAD 16
#define HDIM 64
#define DVDIM 128
#define BATCH 2
#define MROWS (BATCH * S_LEN)   // 4096
#define NQKV 6144
#define WCOLS 8192

#define LAMBDA_INIT_F 0.78360576653162435f
#define ONE_MINUS_LI_F 0.21639423346837565f

// ---------------- scratch (device globals) -------------------------------
__device__ float g_QKV[(size_t)MROWS * NQKV];
__device__ float g_A[(size_t)MROWS * D_EMB];
__device__ float g_lam;

__device__ __nv_bfloat16 g_xhi[(size_t)MROWS * D_EMB];
__device__ __nv_bfloat16 g_xlo[(size_t)MROWS * D_EMB];
__device__ __nv_bfloat16 g_whi[(size_t)D_EMB * WCOLS];   // [K, Wq|Wk|Wv|Wo]
__device__ __nv_bfloat16 g_wlo[(size_t)D_EMB * WCOLS];
__device__ __nv_bfloat16 g_ahi[(size_t)MROWS * D_EMB];
__device__ __nv_bfloat16 g_alo[(size_t)MROWS * D_EMB];

__device__ __nv_bfloat16 g_Qhi[(size_t)MROWS * D_EMB];
__device__ __nv_bfloat16 g_Qlo[(size_t)MROWS * D_EMB];
__device__ __nv_bfloat16 g_Khi[(size_t)MROWS * D_EMB];
__device__ __nv_bfloat16 g_Klo[(size_t)MROWS * D_EMB];
__device__ __nv_bfloat16 g_Vhi[(size_t)MROWS * D_EMB];
__device__ __nv_bfloat16 g_Vlo[(size_t)MROWS * D_EMB];

// ---------------- common PTX helpers --------------------------------------
__device__ __forceinline__ uint32_t smem_u32(const void* p) {
    return (uint32_t)__cvta_generic_to_shared(p);
}
__device__ __forceinline__ void cp16(uint32_t s, const void* g) {
    asm volatile("cp.async.ca.shared.global [%0], [%1], 16;" :: "r"(s), "l"(g));
}
__device__ __forceinline__ void cp16cg(uint32_t s, const void* g) {
    asm volatile("cp.async.cg.shared.global [%0], [%1], 16;" :: "r"(s), "l"(g));
}
__device__ __forceinline__ void ldmx4(uint32_t r[4], uint32_t addr) {
    asm volatile("ldmatrix.sync.aligned.m8n8.x4.shared.b16 {%0,%1,%2,%3}, [%4];"
        : "=r"(r[0]), "=r"(r[1]), "=r"(r[2]), "=r"(r[3]) : "r"(addr));
}
__device__ __forceinline__ void ldmx2t(uint32_t r[2], uint32_t addr) {
    asm volatile("ldmatrix.sync.aligned.m8n8.x2.trans.shared.b16 {%0,%1}, [%2];"
        : "=r"(r[0]), "=r"(r[1]) : "r"(addr));
}
// x4 trans: two n8k16 fragments (cols [c,c+8) and [c+8,c+16))
__device__ __forceinline__ void ldmx4t(uint32_t r[4], uint32_t addr) {
    asm volatile("ldmatrix.sync.aligned.m8n8.x4.trans.shared.b16 {%0,%1,%2,%3}, [%4];"
        : "=r"(r[0]), "=r"(r[1]), "=r"(r[2]), "=r"(r[3]) : "r"(addr));
}
__device__ __forceinline__ void mma_bf16(float c[4], const uint32_t a[4], const uint32_t b[2]) {
    asm volatile("mma.sync.aligned.m16n8k16.row.col.f32.bf16.bf16.f32 "
        "{%0,%1,%2,%3}, {%4,%5,%6,%7}, {%8,%9}, {%0,%1,%2,%3};"
        : "+f"(c[0]), "+f"(c[1]), "+f"(c[2]), "+f"(c[3])
        : "r"(a[0]), "r"(a[1]), "r"(a[2]), "r"(a[3]), "r"(b[0]), "r"(b[1]));
}
__device__ __forceinline__ uint32_t pack_bf16(float lo, float hi) {
    uint32_t r;
    asm("cvt.rn.bf16x2.f32 %0, %1, %2;" : "=r"(r) : "f"(hi), "f"(lo));
    return r;
}
__device__ __forceinline__ float fexp(float x) {
    float t = fmaxf(x, -60.0f) * 1.44269504088896340736f;
    float fi = floorf(t);
    float f = t - fi;
    float p = 1.53964252399628e-4f;
    p = p * f + 1.33336498402e-3f;
    p = p * f + 9.61817668305e-3f;
    p = p * f + 5.55041086648e-2f;
    p = p * f + 2.40226506959101e-1f;
    p = p * f + 6.93147180559945e-1f;
    p = p * f + 1.0f;
    return __int_as_float(__float_as_int(p) + (((int)fi) << 23));
}

// =================== fp32 -> (bf16 hi, bf16 lo) split ====================
__global__ void split_kernel(const float* __restrict__ in,
                             __nv_bfloat16* __restrict__ hi,
                             __nv_bfloat16* __restrict__ lo, int n4)
{
    int i = blockIdx.x * blockDim.x + threadIdx.x;
    if (i >= n4) return;
    float4 v = ((const float4*)in)[i];
    __nv_bfloat16 hx = __float2bfloat16(v.x);
    __nv_bfloat16 hy = __float2bfloat16(v.y);
    __nv_bfloat16 hz = __float2bfloat16(v.z);
    __nv_bfloat16 hw = __float2bfloat16(v.w);
    __nv_bfloat16 lx = __float2bfloat16(v.x - __bfloat162float(hx));
    __nv_bfloat16 ly = __float2bfloat16(v.y - __bfloat162float(hy));
    __nv_bfloat16 lz = __float2bfloat16(v.z - __bfloat162float(hz));
    __nv_bfloat16 lw = __float2bfloat16(v.w - __bfloat162float(hw));
    __nv_bfloat162* H = (__nv_bfloat162*)hi;
    __nv_bfloat162* L = (__nv_bfloat162*)lo;
    H[2 * i]     = __halves2bfloat162(hx, hy);
    H[2 * i + 1] = __halves2bfloat162(hz, hw);
    L[2 * i]     = __halves2bfloat162(lx, ly);
    L[2 * i + 1] = __halves2bfloat162(lz, lw);
}

// ===== W [2048,2048] -> packed [2048, 8192] at column offset + split =====
__global__ void wsplit_kernel(const float* __restrict__ in,
                              __nv_bfloat16* __restrict__ hi,
                              __nv_bfloat16* __restrict__ lo, int colOff)
{
    int i = blockIdx.x * blockDim.x + threadIdx.x;   // over 2048*2048/4
    if (i >= (D_EMB * D_EMB) / 4) return;
    int r = i >> 9;
    int c4 = (i & 511) << 2;
    float4 v = ((const float4*)in)[i];
    __nv_bfloat16 hx = __float2bfloat16(v.x);
    __nv_bfloat16 hy = __float2bfloat16(v.y);
    __nv_bfloat16 hz = __float2bfloat16(v.z);
    __nv_bfloat16 hw = __float2bfloat16(v.w);
    size_t o = (size_t)r * WCOLS + colOff + c4;
    ((__nv_bfloat162*)&hi[o])[0] = __halves2bfloat162(hx, hy);
    ((__nv_bfloat162*)&hi[o])[1] = __halves2bfloat162(hz, hw);
    ((__nv_bfloat162*)&lo[o])[0] = __halves2bfloat162(
        __float2bfloat16(v.x - __bfloat162float(hx)),
        __float2bfloat16(v.y - __bfloat162float(hy)));
    ((__nv_bfloat162*)&lo[o])[1] = __halves2bfloat162(
        __float2bfloat16(v.z - __bfloat162float(hz)),
        __float2bfloat16(v.w - __bfloat162float(hw)));
}

// =================== tensor-core GEMM (bf16 x3 split) ====================
// C[M,N] = A[M,K] * B[K,N]. 512 threads, 128x256 tile, BK=32, 3 stages.
// Warp tile 32x64 (4x4 warp grid). MMA:LDSM = 96:24 per warp-iteration.
#define GBK 32
#define GAP 80                                // A smem pitch bytes (32 bf16 + pad)
#define GBP 528                               // B smem pitch bytes (256 bf16 + pad)
#define GOFF_AL (128 * GAP)                   // 10240
#define GOFF_BH (2 * 128 * GAP)               // 20480
#define GOFF_BL (GOFF_BH + GBK * GBP)         // 37376
#define GSTAGE (GOFF_BL + GBK * GBP)          // 54272
#define G_SMEM (3 * GSTAGE)                   // 162816

__global__ __launch_bounds__(512, 1)
void gemm_bf16x3(const __nv_bfloat16* __restrict__ Ahi, const __nv_bfloat16* __restrict__ Alo,
                 const __nv_bfloat16* __restrict__ Bhi, const __nv_bfloat16* __restrict__ Blo,
                 float* __restrict__ C, int M, int N, int K, int ldb, int ldc)
{
    extern __shared__ __align__(16) uint8_t gsm[];
    const uint32_t sbase = smem_u32(gsm);
    const int tid = threadIdx.x;
    const int lane = tid & 31;
    const int wid = tid >> 5;
    const int m0 = blockIdx.y * 128;
    const int n0 = blockIdx.x * 256;

    const int wm = wid & 3;      // 4 m-tiles of 32 rows
    const int wn = wid >> 2;     // 4 n-slabs of 64 cols

    const int KT = K / GBK;

    // per-stage: A 1024 chunks (128r x 4ch x 2hl), B 2048 (32r x 32ch x 2hl)
    auto load_stage = [&](int t) {
        uint32_t st = sbase + (t % 3) * GSTAGE;
        int k0 = t * GBK;
#pragma unroll
        for (int j = 0; j < 6; j++) {
            int cid = tid + 512 * j;
            if (cid < 1024) {
                int hl = cid >> 9;
                int sub = cid & 511;
                int row = sub >> 2;
                int ch = sub & 3;
                const __nv_bfloat16* src = (hl ? Alo : Ahi)
                    + (size_t)(m0 + row) * K + k0 + ch * 8;
                cp16cg(st + (hl ? GOFF_AL : 0) + row * GAP + ch * 16, src);
            } else {
                int c2 = cid - 1024;
                int hl = c2 >> 10;
                int sub = c2 & 1023;
                int row = sub >> 5;
                int ch = sub & 31;
                const __nv_bfloat16* src = (hl ? Blo : Bhi)
                    + (size_t)(k0 + row) * ldb + n0 + ch * 8;
                cp16cg(st + (hl ? GOFF_BL : GOFF_BH) + row * GBP + ch * 16, src);
            }
        }
        asm volatile("cp.async.commit_group;");
    };

    load_stage(0);
    load_stage(1);
    load_stage(2);

    float acc[2][8][4];
#pragma unroll
    for (int i = 0; i < 2; i++)
#pragma unroll
        for (int j = 0; j < 8; j++)
#pragma unroll
            for (int l = 0; l < 4; l++) acc[i][j][l] = 0.f;

    const uint32_t aoff = (uint32_t)(wm * 32 + (lane & 15)) * GAP + ((lane >> 4) & 1) * 16;
    const uint32_t boff = (uint32_t)(lane & 15) * GBP + (uint32_t)wn * 128
                        + ((lane >> 4) & 1) * 16;

    for (int t = 0; t < KT; t++) {
        int rem = KT - 1 - t;
        if (rem >= 2)      asm volatile("cp.async.wait_group 2;");
        else if (rem == 1) asm volatile("cp.async.wait_group 1;");
        else               asm volatile("cp.async.wait_group 0;");
        __syncthreads();

        uint32_t st = sbase + (t % 3) * GSTAGE;
#pragma unroll
        for (int kk = 0; kk < 2; kk++) {
            uint32_t ah[2][4], al[2][4];
            ldmx4(ah[0], st + aoff + kk * 32);
            ldmx4(ah[1], st + aoff + 16 * GAP + kk * 32);
            ldmx4(al[0], st + GOFF_AL + aoff + kk * 32);
            ldmx4(al[1], st + GOFF_AL + aoff + 16 * GAP + kk * 32);
            uint32_t bb = st + boff + (uint32_t)kk * 16 * GBP;
#pragma unroll
            for (int half = 0; half < 2; half++) {
                uint32_t bh[8], bl[8];   // 4 fragments each
                ldmx4t(&bh[0], bb + GOFF_BH - GOFF_BH + GOFF_BH + half * 64 - GOFF_BH + GOFF_BH);
                // (clean form below; above kept simple:)
                ldmx4t(&bh[0], bb + GOFF_BH + half * 64);
                ldmx4t(&bh[4], bb + GOFF_BH + half * 64 + 32);
                ldmx4t(&bl[0], bb + GOFF_BL + half * 64);
                ldmx4t(&bl[4], bb + GOFF_BL + half * 64 + 32);
#pragma unroll
                for (int mt = 0; mt < 2; mt++)
#pragma unroll
                    for (int nt = 0; nt < 4; nt++) {
                        int ng = half * 4 + nt;
                        mma_bf16(acc[mt][ng], ah[mt], &bh[nt * 2]);
                        mma_bf16(acc[mt][ng], al[mt], &bh[nt * 2]);
                        mma_bf16(acc[mt][ng], ah[mt], &bl[nt * 2]);
                    }
            }
        }
        __syncthreads();
        if (t + 3 < KT) load_stage(t + 3);
    }

    // epilogue
    const int gid = lane >> 2, tig = lane & 3;
#pragma unroll
    for (int mt = 0; mt < 2; mt++) {
        int row = m0 + wm * 32 + mt * 16 + gid;
#pragma unroll
        for (int nt = 0; nt < 8; nt++) {
            int col = n0 + wn * 64 + nt * 8 + 2 * tig;
            *(float2*)&C[(size_t)row * ldc + col] = make_float2(acc[mt][nt][0], acc[mt][nt][1]);
            *(float2*)&C[(size_t)(row + 8) * ldc + col] = make_float2(acc[mt][nt][2], acc[mt][nt][3]);
        }
    }
}

// ---------------- RoPE + bf16 hi/lo split (Q,K from fused QKV) -----------
__global__ void rope_split_kernel(const float* __restrict__ QKV,
                                  __nv_bfloat16* __restrict__ Qhi, __nv_bfloat16* __restrict__ Qlo,
                                  __nv_bfloat16* __restrict__ Khi, __nv_bfloat16* __restrict__ Klo)
{
    const long total = (long)MROWS * (D_EMB / 2);
    const float LN1E4_OVER_32 = 9.210340371976184f / 32.0f;
    for (long p = (long)blockIdx.x * blockDim.x + threadIdx.x; p < total;
         p += (long)gridDim.x * blockDim.x) {
        int pcol = (int)(p & (D_EMB / 2 - 1));
        long row = p >> 10;
        int s = (int)(row & (S_LEN - 1));
        int j = pcol & 31;
        float inv = expf(-(float)j * LN1E4_OVER_32);
        float ang = (float)s * inv;
        float sn, cs;
        sincosf(ang, &sn, &cs);
        size_t idxq = (size_t)row * NQKV + 2 * pcol;
        size_t idxk = idxq + D_EMB;
        size_t pi = (size_t)row * (D_EMB / 2) + pcol;

        float q0 = QKV[idxq], q1 = QKV[idxq + 1];
        float rq0 = q0 * cs - q1 * sn;
        float rq1 = q1 * cs + q0 * sn;
        __nv_bfloat16 qh0 = __float2bfloat16(rq0);
        __nv_bfloat16 qh1 = __float2bfloat16(rq1);
        ((__nv_bfloat162*)Qhi)[pi] = __halves2bfloat162(qh0, qh1);
        ((__nv_bfloat162*)Qlo)[pi] = __halves2bfloat162(
            __float2bfloat16(rq0 - __bfloat162float(qh0)),
            __float2bfloat16(rq1 - __bfloat162float(qh1)));

        float k0 = QKV[idxk], k1 = QKV[idxk + 1];
        float rk0 = k0 * cs - k1 * sn;
        float rk1 = k1 * cs + k0 * sn;
        __nv_bfloat16 kh0 = __float2bfloat16(rk0);
        __nv_bfloat16 kh1 = __float2bfloat16(rk1);
        ((__nv_bfloat162*)Khi)[pi] = __halves2bfloat162(kh0, kh1);
        ((__nv_bfloat162*)Klo)[pi] = __halves2bfloat162(
            __float2bfloat16(rk0 - __bfloat162float(kh0)),
            __float2bfloat16(rk1 - __bfloat162float(kh1)));
    }
}

// ---------------- V split (from fused QKV) --------------------------------
__global__ void vsplit_kernel(const float* __restrict__ QKV,
                              __nv_bfloat16* __restrict__ hi,
                              __nv_bfloat16* __restrict__ lo)
{
    int i = blockIdx.x * blockDim.x + threadIdx.x;
    if (i >= (MROWS * D_EMB) / 4) return;
    int r = i >> 9;
    int c4 = (i & 511) << 2;
    float4 v = *(const float4*)&QKV[(size_t)r * NQKV + 2 * D_EMB + c4];
    __nv_bfloat16 hx = __float2bfloat16(v.x);
    __nv_bfloat16 hy = __float2bfloat16(v.y);
    __nv_bfloat16 hz = __float2bfloat16(v.z);
    __nv_bfloat16 hw = __float2bfloat16(v.w);
    size_t o = (size_t)r * D_EMB + c4;
    ((__nv_bfloat162*)&hi[o])[0] = __halves2bfloat162(hx, hy);
    ((__nv_bfloat162*)&hi[o])[1] = __halves2bfloat162(hz, hw);
    ((__nv_bfloat162*)&lo[o])[0] = __halves2bfloat162(
        __float2bfloat16(v.x - __bfloat162float(hx)),
        __float2bfloat16(v.y - __bfloat162float(hy)));
    ((__nv_bfloat162*)&lo[o])[1] = __halves2bfloat162(
        __float2bfloat16(v.z - __bfloat162float(hz)),
        __float2bfloat16(v.w - __bfloat162float(hw)));
}

// ---------------- lambda scalar ------------------------------------------
__global__ void lam_kernel(const float* __restrict__ lq1, const float* __restrict__ lk1,
                           const float* __restrict__ lq2, const float* __restrict__ lk2)
{
    __shared__ float s1[64], s2[64];
    int t = threadIdx.x;
    s1[t] = lq1[t] * lk1[t];
    s2[t] = lq2[t] * lk2[t];
    __syncthreads();
    if (t == 0) {
        float d1 = 0.f, d2 = 0.f;
        for (int i = 0; i < 64; i++) { d1 += s1[i]; d2 += s2[i]; }
        g_lam = expf(d1) - expf(d2) + LAMBDA_INIT_F;
    }
}

// ================= MMA dual-branch flash attention ========================
#define PQB 144
#define PVB 272
#define QK_TILE (64 * PQB)
#define V_TILE  (64 * PVB)
#define OFF_SQ 0
#define OFF_SK (4 * QK_TILE)
#define OFF_SV (8 * QK_TILE)
#define FL_SMEM (OFF_SV + 2 * V_TILE)

__global__ __launch_bounds__(256, 1)
void flash_mma_kernel(const __nv_bfloat16* __restrict__ Qhi, const __nv_bfloat16* __restrict__ Qlo,
                      const __nv_bfloat16* __restrict__ Khi, const __nv_bfloat16* __restrict__ Klo,
                      const __nv_bfloat16* __restrict__ Vhi, const __nv_bfloat16* __restrict__ Vlo,
                      const float* __restrict__ lnw, const float* __restrict__ lnb,
                      float* __restrict__ Aout)
{
    extern __shared__ __align__(16) uint8_t smraw[];
    const uint32_t sbase = smem_u32(smraw);
    float* sOut = (float*)(smraw + OFF_SK);

    const int tid = threadIdx.x;
    const int lane = tid & 31;
    const int wid = tid >> 5;
    const int br = wid >> 2;
    const int rbase = (wid & 3) * 16;
    const int g = lane >> 2;
    const int tg = lane & 3;

    const int qt = (int)gridDim.x - 1 - (int)blockIdx.x;   // longest CTAs first
    const int h = blockIdx.y;
    const int b = blockIdx.z;
    const int q0t = qt * 64;
    const size_t rowBase = (size_t)b * S_LEN;
    const int colH = h * 128;

#pragma unroll
    for (int it = 0; it < 8; it++) {
        int idx = tid + 256 * it;
        int ch = idx & 7, r = (idx >> 3) & 63, t = idx >> 9;
        const __nv_bfloat16* src = ((t & 1) ? Qlo : Qhi)
            + (rowBase + q0t + r) * D_EMB + colH + (t >> 1) * 64 + ch * 8;
        cp16(sbase + OFF_SQ + t * QK_TILE + r * PQB + ch * 16, src);
    }
    asm volatile("cp.async.commit_group;");
    asm volatile("cp.async.wait_group 0;");
    __syncthreads();

    uint32_t qh[4][4], ql[4][4];
    {
        uint32_t qoff = (uint32_t)(rbase + (lane & 15)) * PQB + ((lane >> 4) << 4);
        uint32_t bh_ = sbase + OFF_SQ + (br * 2) * QK_TILE;
#pragma unroll
        for (int s = 0; s < 4; s++) {
            ldmx4(qh[s], bh_ + qoff + s * 32);
            ldmx4(ql[s], bh_ + QK_TILE + qoff + s * 32);
        }
    }

    float o[16][4];
#pragma unroll
    for (int i = 0; i < 16; i++)
#pragma unroll
        for (int j = 0; j < 4; j++) o[i][j] = 0.f;
    float m_a = -1e30f, m_b = -1e30f, l_a = 0.f, l_b = 0.f;

    for (int kt = 0; kt <= qt; kt++) {
        __syncthreads();
#pragma unroll
        for (int it = 0; it < 8; it++) {
            int idx = tid + 256 * it;
            int ch = idx & 7, r = (idx >> 3) & 63, t = idx >> 9;
            const __nv_bfloat16* src = ((t & 1) ? Klo : Khi)
                + (rowBase + (size_t)kt * 64 + r) * D_EMB + colH + (t >> 1) * 64 + ch * 8;
            cp16(sbase + OFF_SK + t * QK_TILE + r * PQB + ch * 16, src);
        }
#pragma unroll
        for (int it = 0; it < 8; it++) {
            int idx = tid + 256 * it;
            int ch = idx & 15, r = (idx >> 4) & 63, t = idx >> 10;
            const __nv_bfloat16* src = (t ? Vlo : Vhi)
                + (rowBase + (size_t)kt * 64 + r) * D_EMB + colH + ch * 8;
            cp16(sbase + OFF_SV + t * V_TILE + r * PVB + ch * 16, src);
        }
        asm volatile("cp.async.commit_group;");
        asm volatile("cp.async.wait_group 0;");
        __syncthreads();

        float sc[8][4];
#pragma unroll
        for (int i = 0; i < 8; i++)
#pragma unroll
            for (int j = 0; j < 4; j++) sc[i][j] = 0.f;

        const uint32_t kbh = sbase + OFF_SK + (br * 2) * QK_TILE;
        const uint32_t koff = (uint32_t)(lane & 7) * PQB + ((lane >> 3) << 4);
#pragma unroll
        for (int nt = 0; nt < 8; nt++) {
            uint32_t a = koff + (uint32_t)nt * 8 * PQB;
            uint32_t kh0[4], kh1[4], kl0[4], kl1[4];
            ldmx4(kh0, kbh + a);
            ldmx4(kh1, kbh + a + 64);
            ldmx4(kl0, kbh + QK_TILE + a);
            ldmx4(kl1, kbh + QK_TILE + a + 64);
            mma_bf16(sc[nt], qh[0], &kh0[0]);
            mma_bf16(sc[nt], ql[0], &kh0[0]);
            mma_bf16(sc[nt], qh[0], &kl0[0]);
            mma_bf16(sc[nt], qh[1], &kh0[2]);
            mma_bf16(sc[nt], ql[1], &kh0[2]);
            mma_bf16(sc[nt], qh[1], &kl0[2]);
            mma_bf16(sc[nt], qh[2], &kh1[0]);
            mma_bf16(sc[nt], ql[2], &kh1[0]);
            mma_bf16(sc[nt], qh[2], &kl1[0]);
            mma_bf16(sc[nt], qh[3], &kh1[2]);
            mma_bf16(sc[nt], ql[3], &kh1[2]);
            mma_bf16(sc[nt], qh[3], &kl1[2]);
        }

        const bool diag = (kt == qt);
        float mxa = -1e30f, mxb = -1e30f;
#pragma unroll
        for (int nt = 0; nt < 8; nt++) {
            int c0 = nt * 8 + 2 * tg;
#pragma unroll
            for (int e = 0; e < 4; e++) {
                int row = rbase + g + ((e >> 1) << 3);
                int col = c0 + (e & 1);
                float v = sc[nt][e] * 0.125f;
                if (diag && col > row) v = -1e30f;
                sc[nt][e] = v;
            }
            mxa = fmaxf(mxa, fmaxf(sc[nt][0], sc[nt][1]));
            mxb = fmaxf(mxb, fmaxf(sc[nt][2], sc[nt][3]));
        }
        mxa = fmaxf(mxa, __shfl_xor_sync(0xffffffffu, mxa, 1));
        mxa = fmaxf(mxa, __shfl_xor_sync(0xffffffffu, mxa, 2));
        mxb = fmaxf(mxb, __shfl_xor_sync(0xffffffffu, mxb, 1));
        mxb = fmaxf(mxb, __shfl_xor_sync(0xffffffffu, mxb, 2));
        float mna = fmaxf(m_a, mxa), mnb = fmaxf(m_b, mxb);
        float alf_a = fexp(m_a - mna), alf_b = fexp(m_b - mnb);
        m_a = mna; m_b = mnb;

        float suma = 0.f, sumb = 0.f;
        uint32_t ph[4][4], pl[4][4];
#pragma unroll
        for (int s2 = 0; s2 < 4; s2++) {
#pragma unroll
            for (int hf = 0; hf < 2; hf++) {
                int nt = 2 * s2 + hf;
                float p0 = fexp(sc[nt][0] - m_a);
                float p1 = fexp(sc[nt][1] - m_a);
                float p2 = fexp(sc[nt][2] - m_b);
                float p3 = fexp(sc[nt][3] - m_b);
                suma += p0 + p1; sumb += p2 + p3;
                __nv_bfloat16 h0 = __float2bfloat16(p0);
                __nv_bfloat16 h1 = __float2bfloat16(p1);
                __nv_bfloat16 h2 = __float2bfloat16(p2);
                __nv_bfloat16 h3 = __float2bfloat16(p3);
                __nv_bfloat162 t01 = __halves2bfloat162(h0, h1);
                __nv_bfloat162 t23 = __halves2bfloat162(h2, h3);
                ph[s2][hf * 2 + 0] = *(uint32_t*)&t01;
                ph[s2][hf * 2 + 1] = *(uint32_t*)&t23;
                pl[s2][hf * 2 + 0] = pack_bf16(p0 - __bfloat162float(h0),
                                               p1 - __bfloat162float(h1));
                pl[s2][hf * 2 + 1] = pack_bf16(p2 - __bfloat162float(h2),
                                               p3 - __bfloat162float(h3));
            }
        }
        suma += __shfl_xor_sync(0xffffffffu, suma, 1);
        suma += __shfl_xor_sync(0xffffffffu, suma, 2);
        sumb += __shfl_xor_sync(0xffffffffu, sumb, 1);
        sumb += __shfl_xor_sync(0xffffffffu, sumb, 2);
        l_a = alf_a * l_a + suma;
        l_b = alf_b * l_b + sumb;

#pragma unroll
        for (int vt = 0; vt < 16; vt++) {
            o[vt][0] *= alf_a; o[vt][1] *= alf_a;
            o[vt][2] *= alf_b; o[vt][3] *= alf_b;
        }

        const uint32_t vb = sbase + OFF_SV;
        const uint32_t vrow = (uint32_t)(lane & 15) * PVB;
#pragma unroll
        for (int vt = 0; vt < 16; vt++) {
#pragma unroll
            for (int s2 = 0; s2 < 4; s2++) {
                uint32_t addr = (uint32_t)(s2 * 16) * PVB + vrow + vt * 16;
                uint32_t bh[2], bl[2];
                ldmx2t(bh, vb + addr);
                ldmx2t(bl, vb + V_TILE + addr);
                mma_bf16(o[vt], ph[s2], bh);
                mma_bf16(o[vt], pl[s2], bh);
                mma_bf16(o[vt], ph[s2], bl);
            }
        }
    }

    __syncthreads();
    float lam = g_lam;
    float ra = 1.0f / l_a, rb = 1.0f / l_b;

    if (br == 0) {
#pragma unroll
        for (int vt = 0; vt < 16; vt++) {
            int c = vt * 8 + 2 * tg;
            *(float2*)&sOut[(rbase + g) * 128 + c] = make_float2(o[vt][0] * ra, o[vt][1] * ra);
            *(float2*)&sOut[(rbase + g + 8) * 128 + c] = make_float2(o[vt][2] * rb, o[vt][3] * rb);
        }
    }
    __syncthreads();
    if (br == 1) {
#pragma unroll
        for (int vt = 0; vt < 16; vt++) {
            int c = vt * 8 + 2 * tg;
            float2* p0 = (float2*)&sOut[(rbase + g) * 128 + c];
            float2 v0 = *p0;
            v0.x -= lam * o[vt][0] * ra; v0.y -= lam * o[vt][1] * ra;
            *p0 = v0;
            float2* p1 = (float2*)&sOut[(rbase + g + 8) * 128 + c];
            float2 v1 = *p1;
            v1.x -= lam * o[vt][2] * rb; v1.y -= lam * o[vt][3] * rb;
            *p1 = v1;
        }
    }
    __syncthreads();

    {
        int r = tid >> 2;
        int q4 = tid & 3;
        float ss = 0.f;
#pragma unroll
        for (int u = 0; u < 32; u++) {
            float v = sOut[r * 128 + q4 * 32 + u];
            ss += v * v;
        }
        ss += __shfl_xor_sync(0xffffffffu, ss, 1);
        ss += __shfl_xor_sync(0xffffffffu, ss, 2);
        float rn = rsqrtf(ss * (1.0f / 128.0f) + 1e-8f);
        size_t outrow = (rowBase + q0t + r) * D_EMB + colH;
#pragma unroll
        for (int u = 0; u < 32; u++) {
            int e = q4 * 32 + u;
            Aout[outrow + e] = (sOut[r * 128 + e] * rn * lnw[e] + lnb[e]) * ONE_MINUS_LI_F;
        }
    }
}

// ---------------- launch ---------------------------------------------------
extern "C" void kernel_launch(void* const* d_in, const int* in_sizes, int n_in,
                              void* d_out, int out_size)
{
    (void)in_sizes; (void)n_in; (void)out_size;
    const float* x   = (const float*)d_in[0];
    const float* Wq  = (const float*)d_in[1];
    const float* Wk  = (const float*)d_in[2];
    const float* Wv  = (const float*)d_in[3];
    const float* Wo  = (const float*)d_in[4];
    const float* lq1 = (const float*)d_in[5];
    const float* lk1 = (const float*)d_in[6];
    const float* lq2 = (const float*)d_in[7];
    const float* lk2 = (const float*)d_in[8];
    const float* lnw = (const float*)d_in[9];
    const float* lnb = (const float*)d_in[10];
    float* out = (float*)d_out;

    float *qkv, *ap;
    cudaGetSymbolAddress((void**)&qkv, g_QKV);
    cudaGetSymbolAddress((void**)&ap, g_A);

    __nv_bfloat16 *xhi, *xlo, *whi, *wlo, *ahi, *alo;
    __nv_bfloat16 *qhi, *qlo, *khi, *klo, *vhi, *vlo;
    cudaGetSymbolAddress((void**)&xhi, g_xhi);
    cudaGetSymbolAddress((void**)&xlo, g_xlo);
    cudaGetSymbolAddress((void**)&whi, g_whi);
    cudaGetSymbolAddress((void**)&wlo, g_wlo);
    cudaGetSymbolAddress((void**)&ahi, g_ahi);
    cudaGetSymbolAddress((void**)&alo, g_alo);
    cudaGetSymbolAddress((void**)&qhi, g_Qhi);
    cudaGetSymbolAddress((void**)&qlo, g_Qlo);
    cudaGetSymbolAddress((void**)&khi, g_Khi);
    cudaGetSymbolAddress((void**)&klo, g_Klo);
    cudaGetSymbolAddress((void**)&vhi, g_Vhi);
    cudaGetSymbolAddress((void**)&vlo, g_Vlo);

    const int nx4 = (MROWS * D_EMB) / 4;
    const int nw4 = (D_EMB * D_EMB) / 4;

    split_kernel<<<(nx4 + 255) / 256, 256>>>(x, xhi, xlo, nx4);
    wsplit_kernel<<<(nw4 + 255) / 256, 256>>>(Wq, whi, wlo, 0);
    wsplit_kernel<<<(nw4 + 255) / 256, 256>>>(Wk, whi, wlo, 2048);
    wsplit_kernel<<<(nw4 + 255) / 256, 256>>>(Wv, whi, wlo, 4096);
    wsplit_kernel<<<(nw4 + 255) / 256, 256>>>(Wo, whi, wlo, 6144);

    cudaFuncSetAttribute(gemm_bf16x3, cudaFuncAttributeMaxDynamicSharedMemorySize, G_SMEM);

    // fused QKV projection: [4096, 2048] x [2048, 6144]
    dim3 gqkv(NQKV / 256, MROWS / 128);   // (24, 32)
    gemm_bf16x3<<<gqkv, 512, G_SMEM>>>(xhi, xlo, whi, wlo, qkv,
                                       MROWS, NQKV, D_EMB, WCOLS, NQKV);

    rope_split_kernel<<<2048, 256>>>(qkv, qhi, qlo, khi, klo);
    vsplit_kernel<<<(nx4 + 255) / 256, 256>>>(qkv, vhi, vlo);
    lam_kernel<<<1, 64>>>(lq1, lk1, lq2, lk2);

    cudaFuncSetAttribute(flash_mma_kernel, cudaFuncAttributeMaxDynamicSharedMemorySize, FL_SMEM);
    flash_mma_kernel<<<dim3(32, NHEAD, BATCH), 256, FL_SMEM>>>(
        qhi, qlo, khi, klo, vhi, vlo, lnw, lnb, ap);

    split_kernel<<<(nx4 + 255) / 256, 256>>>(ap, ahi, alo, nx4);

    // output projection: [4096, 2048] x [2048, 2048]
    dim3 go(D_EMB / 256, MROWS / 128);    // (8, 32)
    gemm_bf16x3<<<go, 512, G_SMEM>>>(ahi, alo, whi + 6144, wlo + 6144, out,
                                     MROWS, D_EMB, D_EMB, WCOLS, D_EMB);
}

// round 7
// speedup vs baseline: 1.1302x; 1.0169x over previous
#include <cuda_runtime.h>
#include <cuda_bf16.h>
#include <cstdint>
#include <cstddef>

#define S_LEN 2048
#define D_EMB 2048
#define NHEAD 16
#define HDIM 64
#define DVDIM 128
#define BATCH 2
#define MROWS (BATCH * S_LEN)   // 4096
#define NQKV 6144
#define WCOLS 8192

#define LAMBDA_INIT_F 0.78360576653162435f
#define ONE_MINUS_LI_F 0.21639423346837565f
#define LN1E4_OVER_32 (9.210340371976184f / 32.0f)

// ---------------- scratch (device globals) -------------------------------
__device__ float g_lam;
__device__ float2 g_rope[S_LEN * 32];          // [s][j] -> (cos, sin)

__device__ __nv_bfloat16 g_xhi[(size_t)MROWS * D_EMB];
__device__ __nv_bfloat16 g_xlo[(size_t)MROWS * D_EMB];
__device__ __nv_bfloat16 g_whi[(size_t)D_EMB * WCOLS];   // [K, Wq|Wk|Wv|Wo]
__device__ __nv_bfloat16 g_wlo[(size_t)D_EMB * WCOLS];
__device__ __nv_bfloat16 g_ahi[(size_t)MROWS * D_EMB];
__device__ __nv_bfloat16 g_alo[(size_t)MROWS * D_EMB];

__device__ __nv_bfloat16 g_Qhi[(size_t)MROWS * D_EMB];
__device__ __nv_bfloat16 g_Qlo[(size_t)MROWS * D_EMB];
__device__ __nv_bfloat16 g_Khi[(size_t)MROWS * D_EMB];
__device__ __nv_bfloat16 g_Klo[(size_t)MROWS * D_EMB];
__device__ __nv_bfloat16 g_Vhi[(size_t)MROWS * D_EMB];
__device__ __nv_bfloat16 g_Vlo[(size_t)MROWS * D_EMB];

// ---------------- common PTX helpers --------------------------------------
__device__ __forceinline__ uint32_t smem_u32(const void* p) {
    return (uint32_t)__cvta_generic_to_shared(p);
}
__device__ __forceinline__ void cp16(uint32_t s, const void* g) {
    asm volatile("cp.async.ca.shared.global [%0], [%1], 16;" :: "r"(s), "l"(g));
}
__device__ __forceinline__ void cp16cg(uint32_t s, const void* g) {
    asm volatile("cp.async.cg.shared.global [%0], [%1], 16;" :: "r"(s), "l"(g));
}
__device__ __forceinline__ void ldmx4(uint32_t r[4], uint32_t addr) {
    asm volatile("ldmatrix.sync.aligned.m8n8.x4.shared.b16 {%0,%1,%2,%3}, [%4];"
        : "=r"(r[0]), "=r"(r[1]), "=r"(r[2]), "=r"(r[3]) : "r"(addr));
}
__device__ __forceinline__ void ldmx2t(uint32_t r[2], uint32_t addr) {
    asm volatile("ldmatrix.sync.aligned.m8n8.x2.trans.shared.b16 {%0,%1}, [%2];"
        : "=r"(r[0]), "=r"(r[1]) : "r"(addr));
}
__device__ __forceinline__ void ldmx4t(uint32_t r[4], uint32_t addr) {
    asm volatile("ldmatrix.sync.aligned.m8n8.x4.trans.shared.b16 {%0,%1,%2,%3}, [%4];"
        : "=r"(r[0]), "=r"(r[1]), "=r"(r[2]), "=r"(r[3]) : "r"(addr));
}
__device__ __forceinline__ void mma_bf16(float c[4], const uint32_t a[4], const uint32_t b[2]) {
    asm volatile("mma.sync.aligned.m16n8k16.row.col.f32.bf16.bf16.f32 "
        "{%0,%1,%2,%3}, {%4,%5,%6,%7}, {%8,%9}, {%0,%1,%2,%3};"
        : "+f"(c[0]), "+f"(c[1]), "+f"(c[2]), "+f"(c[3])
        : "r"(a[0]), "r"(a[1]), "r"(a[2]), "r"(a[3]), "r"(b[0]), "r"(b[1]));
}
__device__ __forceinline__ uint32_t pack_bf16(float lo, float hi) {
    uint32_t r;
    asm("cvt.rn.bf16x2.f32 %0, %1, %2;" : "=r"(r) : "f"(hi), "f"(lo));
    return r;
}
__device__ __forceinline__ float fexp(float x) {
    float t = fmaxf(x, -60.0f) * 1.44269504088896340736f;
    float fi = floorf(t);
    float f = t - fi;
    float p = 1.53964252399628e-4f;
    p = p * f + 1.33336498402e-3f;
    p = p * f + 9.61817668305e-3f;
    p = p * f + 5.55041086648e-2f;
    p = p * f + 2.40226506959101e-1f;
    p = p * f + 6.93147180559945e-1f;
    p = p * f + 1.0f;
    return __int_as_float(__float_as_int(p) + (((int)fi) << 23));
}
// split one fp32 pair -> (hi bf16x2, lo bf16x2)
__device__ __forceinline__ void split2(float v0, float v1, uint32_t& hw, uint32_t& lw) {
    __nv_bfloat16 h0 = __float2bfloat16(v0);
    __nv_bfloat16 h1 = __float2bfloat16(v1);
    __nv_bfloat162 hh = __halves2bfloat162(h0, h1);
    hw = *(uint32_t*)&hh;
    lw = pack_bf16(v0 - __bfloat162float(h0), v1 - __bfloat162float(h1));
}

// =================== fp32 -> (bf16 hi, bf16 lo) split ====================
__global__ void split_kernel(const float* __restrict__ in,
                             __nv_bfloat16* __restrict__ hi,
                             __nv_bfloat16* __restrict__ lo, int n4)
{
    int i = blockIdx.x * blockDim.x + threadIdx.x;
    if (i >= n4) return;
    float4 v = ((const float4*)in)[i];
    uint32_t h0, l0, h1, l1;
    split2(v.x, v.y, h0, l0);
    split2(v.z, v.w, h1, l1);
    ((uint32_t*)hi)[2 * i]     = h0;
    ((uint32_t*)hi)[2 * i + 1] = h1;
    ((uint32_t*)lo)[2 * i]     = l0;
    ((uint32_t*)lo)[2 * i + 1] = l1;
}

// ===== W [2048,2048] -> packed [2048, 8192] at column offset + split =====
// doTable: first 256 blocks also fill the rope cos/sin table.
__global__ void wsplit_kernel(const float* __restrict__ in,
                              __nv_bfloat16* __restrict__ hi,
                              __nv_bfloat16* __restrict__ lo, int colOff, int doTable)
{
    if (doTable && blockIdx.x < 256) {
        int idx = blockIdx.x * 256 + threadIdx.x;   // 65536 = 2048*32
        int s = idx >> 5, j = idx & 31;
        float inv = expf(-(float)j * LN1E4_OVER_32);
        float sn, cs;
        sincosf((float)s * inv, &sn, &cs);
        g_rope[idx] = make_float2(cs, sn);
    }
    int i = blockIdx.x * blockDim.x + threadIdx.x;
    if (i >= (D_EMB * D_EMB) / 4) return;
    int r = i >> 9;
    int c4 = (i & 511) << 2;
    float4 v = ((const float4*)in)[i];
    uint32_t h0, l0, h1, l1;
    split2(v.x, v.y, h0, l0);
    split2(v.z, v.w, h1, l1);
    size_t o = ((size_t)r * WCOLS + colOff + c4) >> 1;
    ((uint32_t*)hi)[o]     = h0;
    ((uint32_t*)hi)[o + 1] = h1;
    ((uint32_t*)lo)[o]     = l0;
    ((uint32_t*)lo)[o + 1] = l1;
}

// =================== tensor-core GEMM (bf16 x3 split) ====================
// C[M,N] = A[M,K] * B[K,N]. 512 threads, 128x256 tile, BK=32, 3 stages.
// MODE 0: fp32 store to C. MODE 1: fused rope + bf16 hi/lo split to Q/K/V.
#define GBK 32
#define GAP 80
#define GBP 528
#define GOFF_AL (128 * GAP)
#define GOFF_BH (2 * 128 * GAP)
#define GOFF_BL (GOFF_BH + GBK * GBP)
#define GSTAGE (GOFF_BL + GBK * GBP)
#define G_SMEM (3 * GSTAGE)

template <int MODE>
__global__ __launch_bounds__(512, 1)
void gemm_bf16x3(const __nv_bfloat16* __restrict__ Ahi, const __nv_bfloat16* __restrict__ Alo,
                 const __nv_bfloat16* __restrict__ Bhi, const __nv_bfloat16* __restrict__ Blo,
                 float* __restrict__ C, int M, int N, int K, int ldb, int ldc)
{
    extern __shared__ __align__(16) uint8_t gsm[];
    const uint32_t sbase = smem_u32(gsm);
    const int tid = threadIdx.x;
    const int lane = tid & 31;
    const int wid = tid >> 5;
    const int m0 = blockIdx.y * 128;
    const int n0 = blockIdx.x * 256;

    const int wm = wid & 3;
    const int wn = wid >> 2;

    const int KT = K / GBK;

    auto load_stage = [&](int t) {
        uint32_t st = sbase + (t % 3) * GSTAGE;
        int k0 = t * GBK;
#pragma unroll
        for (int j = 0; j < 6; j++) {
            int cid = tid + 512 * j;
            if (cid < 1024) {
                int hl = cid >> 9;
                int sub = cid & 511;
                int row = sub >> 2;
                int ch = sub & 3;
                const __nv_bfloat16* src = (hl ? Alo : Ahi)
                    + (size_t)(m0 + row) * K + k0 + ch * 8;
                cp16cg(st + (hl ? GOFF_AL : 0) + row * GAP + ch * 16, src);
            } else {
                int c2 = cid - 1024;
                int hl = c2 >> 10;
                int sub = c2 & 1023;
                int row = sub >> 5;
                int ch = sub & 31;
                const __nv_bfloat16* src = (hl ? Blo : Bhi)
                    + (size_t)(k0 + row) * ldb + n0 + ch * 8;
                cp16cg(st + (hl ? GOFF_BL : GOFF_BH) + row * GBP + ch * 16, src);
            }
        }
        asm volatile("cp.async.commit_group;");
    };

    load_stage(0);
    load_stage(1);
    load_stage(2);

    float acc[2][8][4];
#pragma unroll
    for (int i = 0; i < 2; i++)
#pragma unroll
        for (int j = 0; j < 8; j++)
#pragma unroll
            for (int l = 0; l < 4; l++) acc[i][j][l] = 0.f;

    const uint32_t aoff = (uint32_t)(wm * 32 + (lane & 15)) * GAP + ((lane >> 4) & 1) * 16;
    const uint32_t boff = (uint32_t)(lane & 15) * GBP + (uint32_t)wn * 128
                        + ((lane >> 4) & 1) * 16;

    for (int t = 0; t < KT; t++) {
        int rem = KT - 1 - t;
        if (rem >= 2)      asm volatile("cp.async.wait_group 2;");
        else if (rem == 1) asm volatile("cp.async.wait_group 1;");
        else               asm volatile("cp.async.wait_group 0;");
        __syncthreads();

        uint32_t st = sbase + (t % 3) * GSTAGE;
#pragma unroll
        for (int kk = 0; kk < 2; kk++) {
            uint32_t ah[2][4], al[2][4];
            ldmx4(ah[0], st + aoff + kk * 32);
            ldmx4(ah[1], st + aoff + 16 * GAP + kk * 32);
            ldmx4(al[0], st + GOFF_AL + aoff + kk * 32);
            ldmx4(al[1], st + GOFF_AL + aoff + 16 * GAP + kk * 32);
            uint32_t bb = st + boff + (uint32_t)kk * 16 * GBP;
#pragma unroll
            for (int half = 0; half < 2; half++) {
                uint32_t bh[8], bl[8];
                ldmx4t(&bh[0], bb + GOFF_BH + half * 64);
                ldmx4t(&bh[4], bb + GOFF_BH + half * 64 + 32);
                ldmx4t(&bl[0], bb + GOFF_BL + half * 64);
                ldmx4t(&bl[4], bb + GOFF_BL + half * 64 + 32);
#pragma unroll
                for (int mt = 0; mt < 2; mt++)
#pragma unroll
                    for (int nt = 0; nt < 4; nt++) {
                        int ng = half * 4 + nt;
                        mma_bf16(acc[mt][ng], ah[mt], &bh[nt * 2]);
                        mma_bf16(acc[mt][ng], al[mt], &bh[nt * 2]);
                        mma_bf16(acc[mt][ng], ah[mt], &bl[nt * 2]);
                    }
            }
        }
        __syncthreads();
        if (t + 3 < KT) load_stage(t + 3);
    }

    // epilogue
    const int gid = lane >> 2, tig = lane & 3;
    if (MODE == 0) {
#pragma unroll
        for (int mt = 0; mt < 2; mt++) {
            int row = m0 + wm * 32 + mt * 16 + gid;
#pragma unroll
            for (int nt = 0; nt < 8; nt++) {
                int col = n0 + wn * 64 + nt * 8 + 2 * tig;
                *(float2*)&C[(size_t)row * ldc + col] = make_float2(acc[mt][nt][0], acc[mt][nt][1]);
                *(float2*)&C[(size_t)(row + 8) * ldc + col] = make_float2(acc[mt][nt][2], acc[mt][nt][3]);
            }
        }
    } else {
        // fused rope (Q,K) / plain (V) + bf16 hi/lo split stores
        const int region = n0 >> 11;    // 0=Q, 1=K, 2=V (whole CTA same region)
        __nv_bfloat16* dh = (region == 0) ? g_Qhi : (region == 1) ? g_Khi : g_Vhi;
        __nv_bfloat16* dl = (region == 0) ? g_Qlo : (region == 1) ? g_Klo : g_Vlo;
#pragma unroll
        for (int mt = 0; mt < 2; mt++) {
#pragma unroll
            for (int nt = 0; nt < 8; nt++) {
                int col = n0 + wn * 64 + nt * 8 + 2 * tig;
                int cl = col & 2047;
                int j = (cl & 63) >> 1;
#pragma unroll
                for (int rr = 0; rr < 2; rr++) {
                    int row = m0 + wm * 32 + mt * 16 + gid + rr * 8;
                    float v0 = acc[mt][nt][rr * 2 + 0];
                    float v1 = acc[mt][nt][rr * 2 + 1];
                    if (region < 2) {
                        int s = row & (S_LEN - 1);
                        float2 t = g_rope[(s << 5) + j];
                        float f0 = v0 * t.x - v1 * t.y;
                        float f1 = v1 * t.x + v0 * t.y;
                        v0 = f0; v1 = f1;
                    }
                    uint32_t hw, lw;
                    split2(v0, v1, hw, lw);
                    size_t o = ((size_t)row * D_EMB + cl) >> 1;
                    ((uint32_t*)dh)[o] = hw;
                    ((uint32_t*)dl)[o] = lw;
                }
            }
        }
    }
}

// ---------------- lambda scalar ------------------------------------------
__global__ void lam_kernel(const float* __restrict__ lq1, const float* __restrict__ lk1,
                           const float* __restrict__ lq2, const float* __restrict__ lk2)
{
    __shared__ float s1[64], s2[64];
    int t = threadIdx.x;
    s1[t] = lq1[t] * lk1[t];
    s2[t] = lq2[t] * lk2[t];
    __syncthreads();
    if (t == 0) {
        float d1 = 0.f, d2 = 0.f;
        for (int i = 0; i < 64; i++) { d1 += s1[i]; d2 += s2[i]; }
        g_lam = expf(d1) - expf(d2) + LAMBDA_INIT_F;
    }
}

// ================= MMA dual-branch flash attention (double-buffered) ======
#define PQB 144
#define PVB 272
#define QK_TILE (64 * PQB)              // 9216
#define V_TILE  (64 * PVB)              // 17408
#define FOFF_Q 0                        // 4 Q tiles
#define FSTG (4 * QK_TILE + 2 * V_TILE) // 71680 per stage (K tiles + V tiles)
#define FOFF_S0 (4 * QK_TILE)           // 36864
#define FL_SMEM (FOFF_S0 + 2 * FSTG)    // 180224

__global__ __launch_bounds__(256, 1)
void flash_mma_kernel(const __nv_bfloat16* __restrict__ Qhi, const __nv_bfloat16* __restrict__ Qlo,
                      const __nv_bfloat16* __restrict__ Khi, const __nv_bfloat16* __restrict__ Klo,
                      const __nv_bfloat16* __restrict__ Vhi, const __nv_bfloat16* __restrict__ Vlo,
                      const float* __restrict__ lnw, const float* __restrict__ lnb,
                      __nv_bfloat16* __restrict__ Ahi, __nv_bfloat16* __restrict__ Alo)
{
    extern __shared__ __align__(16) uint8_t smraw[];
    const uint32_t sbase = smem_u32(smraw);
    float* sOut = (float*)smraw;        // overlays Q region after loop (32KB < 36KB)

    const int tid = threadIdx.x;
    const int lane = tid & 31;
    const int wid = tid >> 5;
    const int br = wid >> 2;
    const int rbase = (wid & 3) * 16;
    const int g = lane >> 2;
    const int tg = lane & 3;

    const int qt = (int)gridDim.x - 1 - (int)blockIdx.x;
    const int h = blockIdx.y;
    const int b = blockIdx.z;
    const int q0t = qt * 64;
    const size_t rowBase = (size_t)b * S_LEN;
    const int colH = h * 128;

    // ---- Q tiles ----
#pragma unroll
    for (int it = 0; it < 8; it++) {
        int idx = tid + 256 * it;
        int ch = idx & 7, r = (idx >> 3) & 63, t = idx >> 9;
        const __nv_bfloat16* src = ((t & 1) ? Qlo : Qhi)
            + (rowBase + q0t + r) * D_EMB + colH + (t >> 1) * 64 + ch * 8;
        cp16(sbase + FOFF_Q + t * QK_TILE + r * PQB + ch * 16, src);
    }
    asm volatile("cp.async.commit_group;");
    asm volatile("cp.async.wait_group 0;");
    __syncthreads();

    uint32_t qh[4][4], ql[4][4];
    {
        uint32_t qoff = (uint32_t)(rbase + (lane & 15)) * PQB + ((lane >> 4) << 4);
        uint32_t bh_ = sbase + FOFF_Q + (br * 2) * QK_TILE;
#pragma unroll
        for (int s = 0; s < 4; s++) {
            ldmx4(qh[s], bh_ + qoff + s * 32);
            ldmx4(ql[s], bh_ + QK_TILE + qoff + s * 32);
        }
    }

    auto load_kv = [&](int kt) {
        uint32_t stb = sbase + FOFF_S0 + (kt & 1) * FSTG;
#pragma unroll
        for (int it = 0; it < 8; it++) {
            int idx = tid + 256 * it;
            int ch = idx & 7, r = (idx >> 3) & 63, t = idx >> 9;
            const __nv_bfloat16* src = ((t & 1) ? Klo : Khi)
                + (rowBase + (size_t)kt * 64 + r) * D_EMB + colH + (t >> 1) * 64 + ch * 8;
            cp16(stb + t * QK_TILE + r * PQB + ch * 16, src);
        }
#pragma unroll
        for (int it = 0; it < 8; it++) {
            int idx = tid + 256 * it;
            int ch = idx & 15, r = (idx >> 4) & 63, t = idx >> 10;
            const __nv_bfloat16* src = (t ? Vlo : Vhi)
                + (rowBase + (size_t)kt * 64 + r) * D_EMB + colH + ch * 8;
            cp16(stb + 4 * QK_TILE + t * V_TILE + r * PVB + ch * 16, src);
        }
        asm volatile("cp.async.commit_group;");
    };

    float o[16][4];
#pragma unroll
    for (int i = 0; i < 16; i++)
#pragma unroll
        for (int j = 0; j < 4; j++) o[i][j] = 0.f;
    float m_a = -1e30f, m_b = -1e30f, l_a = 0.f, l_b = 0.f;

    load_kv(0);

    for (int kt = 0; kt <= qt; kt++) {
        if (kt < qt) {
            load_kv(kt + 1);
            asm volatile("cp.async.wait_group 1;");
        } else {
            asm volatile("cp.async.wait_group 0;");
        }
        __syncthreads();

        const uint32_t stb = sbase + FOFF_S0 + (kt & 1) * FSTG;

        float sc[8][4];
#pragma unroll
        for (int i = 0; i < 8; i++)
#pragma unroll
            for (int j = 0; j < 4; j++) sc[i][j] = 0.f;

        const uint32_t kbh = stb + (br * 2) * QK_TILE;
        const uint32_t koff = (uint32_t)(lane & 7) * PQB + ((lane >> 3) << 4);
#pragma unroll
        for (int nt = 0; nt < 8; nt++) {
            uint32_t a = koff + (uint32_t)nt * 8 * PQB;
            uint32_t kh0[4], kh1[4], kl0[4], kl1[4];
            ldmx4(kh0, kbh + a);
            ldmx4(kh1, kbh + a + 64);
            ldmx4(kl0, kbh + QK_TILE + a);
            ldmx4(kl1, kbh + QK_TILE + a + 64);
            mma_bf16(sc[nt], qh[0], &kh0[0]);
            mma_bf16(sc[nt], ql[0], &kh0[0]);
            mma_bf16(sc[nt], qh[0], &kl0[0]);
            mma_bf16(sc[nt], qh[1], &kh0[2]);
            mma_bf16(sc[nt], ql[1], &kh0[2]);
            mma_bf16(sc[nt], qh[1], &kl0[2]);
            mma_bf16(sc[nt], qh[2], &kh1[0]);
            mma_bf16(sc[nt], ql[2], &kh1[0]);
            mma_bf16(sc[nt], qh[2], &kl1[0]);
            mma_bf16(sc[nt], qh[3], &kh1[2]);
            mma_bf16(sc[nt], ql[3], &kh1[2]);
            mma_bf16(sc[nt], qh[3], &kl1[2]);
        }

        const bool diag = (kt == qt);
        float mxa = -1e30f, mxb = -1e30f;
#pragma unroll
        for (int nt = 0; nt < 8; nt++) {
            int c0 = nt * 8 + 2 * tg;
#pragma unroll
            for (int e = 0; e < 4; e++) {
                int row = rbase + g + ((e >> 1) << 3);
                int col = c0 + (e & 1);
                float v = sc[nt][e] * 0.125f;
                if (diag && col > row) v = -1e30f;
                sc[nt][e] = v;
            }
            mxa = fmaxf(mxa, fmaxf(sc[nt][0], sc[nt][1]));
            mxb = fmaxf(mxb, fmaxf(sc[nt][2], sc[nt][3]));
        }
        mxa = fmaxf(mxa, __shfl_xor_sync(0xffffffffu, mxa, 1));
        mxa = fmaxf(mxa, __shfl_xor_sync(0xffffffffu, mxa, 2));
        mxb = fmaxf(mxb, __shfl_xor_sync(0xffffffffu, mxb, 1));
        mxb = fmaxf(mxb, __shfl_xor_sync(0xffffffffu, mxb, 2));
        float mna = fmaxf(m_a, mxa), mnb = fmaxf(m_b, mxb);
        float alf_a = fexp(m_a - mna), alf_b = fexp(m_b - mnb);
        m_a = mna; m_b = mnb;

        float suma = 0.f, sumb = 0.f;
        uint32_t ph[4][4], pl[4][4];
#pragma unroll
        for (int s2 = 0; s2 < 4; s2++) {
#pragma unroll
            for (int hf = 0; hf < 2; hf++) {
                int nt = 2 * s2 + hf;
                float p0 = fexp(sc[nt][0] - m_a);
                float p1 = fexp(sc[nt][1] - m_a);
                float p2 = fexp(sc[nt][2] - m_b);
                float p3 = fexp(sc[nt][3] - m_b);
                suma += p0 + p1; sumb += p2 + p3;
                __nv_bfloat16 h0 = __float2bfloat16(p0);
                __nv_bfloat16 h1 = __float2bfloat16(p1);
                __nv_bfloat16 h2 = __float2bfloat16(p2);
                __nv_bfloat16 h3 = __float2bfloat16(p3);
                __nv_bfloat162 t01 = __halves2bfloat162(h0, h1);
                __nv_bfloat162 t23 = __halves2bfloat162(h2, h3);
                ph[s2][hf * 2 + 0] = *(uint32_t*)&t01;
                ph[s2][hf * 2 + 1] = *(uint32_t*)&t23;
                pl[s2][hf * 2 + 0] = pack_bf16(p0 - __bfloat162float(h0),
                                               p1 - __bfloat162float(h1));
                pl[s2][hf * 2 + 1] = pack_bf16(p2 - __bfloat162float(h2),
                                               p3 - __bfloat162float(h3));
            }
        }
        suma += __shfl_xor_sync(0xffffffffu, suma, 1);
        suma += __shfl_xor_sync(0xffffffffu, suma, 2);
        sumb += __shfl_xor_sync(0xffffffffu, sumb, 1);
        sumb += __shfl_xor_sync(0xffffffffu, sumb, 2);
        l_a = alf_a * l_a + suma;
        l_b = alf_b * l_b + sumb;

#pragma unroll
        for (int vt = 0; vt < 16; vt++) {
            o[vt][0] *= alf_a; o[vt][1] *= alf_a;
            o[vt][2] *= alf_b; o[vt][3] *= alf_b;
        }

        const uint32_t vb = stb + 4 * QK_TILE;
        const uint32_t vrow = (uint32_t)(lane & 15) * PVB;
#pragma unroll
        for (int vt = 0; vt < 16; vt++) {
#pragma unroll
            for (int s2 = 0; s2 < 4; s2++) {
                uint32_t addr = (uint32_t)(s2 * 16) * PVB + vrow + vt * 16;
                uint32_t bh[2], bl[2];
                ldmx2t(bh, vb + addr);
                ldmx2t(bl, vb + V_TILE + addr);
                mma_bf16(o[vt], ph[s2], bh);
                mma_bf16(o[vt], pl[s2], bh);
                mma_bf16(o[vt], ph[s2], bl);
            }
        }
        __syncthreads();
    }

    float lam = g_lam;
    float ra = 1.0f / l_a, rb = 1.0f / l_b;

    if (br == 0) {
#pragma unroll
        for (int vt = 0; vt < 16; vt++) {
            int c = vt * 8 + 2 * tg;
            *(float2*)&sOut[(rbase + g) * 128 + c] = make_float2(o[vt][0] * ra, o[vt][1] * ra);
            *(float2*)&sOut[(rbase + g + 8) * 128 + c] = make_float2(o[vt][2] * rb, o[vt][3] * rb);
        }
    }
    __syncthreads();
    if (br == 1) {
#pragma unroll
        for (int vt = 0; vt < 16; vt++) {
            int c = vt * 8 + 2 * tg;
            float2* p0 = (float2*)&sOut[(rbase + g) * 128 + c];
            float2 v0 = *p0;
            v0.x -= lam * o[vt][0] * ra; v0.y -= lam * o[vt][1] * ra;
            *p0 = v0;
            float2* p1 = (float2*)&sOut[(rbase + g + 8) * 128 + c];
            float2 v1 = *p1;
            v1.x -= lam * o[vt][2] * rb; v1.y -= lam * o[vt][3] * rb;
            *p1 = v1;
        }
    }
    __syncthreads();

    // ---- RMSNorm + scale + split bf16 write ----
    {
        int r = tid >> 2;
        int q4 = tid & 3;
        float ss = 0.f;
#pragma unroll
        for (int u = 0; u < 32; u++) {
            float v = sOut[r * 128 + q4 * 32 + u];
            ss += v * v;
        }
        ss += __shfl_xor_sync(0xffffffffu, ss, 1);
        ss += __shfl_xor_sync(0xffffffffu, ss, 2);
        float rn = rsqrtf(ss * (1.0f / 128.0f) + 1e-8f);
        size_t outrow = (rowBase + q0t + r) * D_EMB + colH;
#pragma unroll
        for (int u = 0; u < 32; u += 2) {
            int e = q4 * 32 + u;
            float v0 = (sOut[r * 128 + e] * rn * lnw[e] + lnb[e]) * ONE_MINUS_LI_F;
            float v1 = (sOut[r * 128 + e + 1] * rn * lnw[e + 1] + lnb[e + 1]) * ONE_MINUS_LI_F;
            uint32_t hw, lw;
            split2(v0, v1, hw, lw);
            *(uint32_t*)&Ahi[outrow + e] = hw;
            *(uint32_t*)&Alo[outrow + e] = lw;
        }
    }
}

// ---------------- launch ---------------------------------------------------
extern "C" void kernel_launch(void* const* d_in, const int* in_sizes, int n_in,
                              void* d_out, int out_size)
{
    (void)in_sizes; (void)n_in; (void)out_size;
    const float* x   = (const float*)d_in[0];
    const float* Wq  = (const float*)d_in[1];
    const float* Wk  = (const float*)d_in[2];
    const float* Wv  = (const float*)d_in[3];
    const float* Wo  = (const float*)d_in[4];
    const float* lq1 = (const float*)d_in[5];
    const float* lk1 = (const float*)d_in[6];
    const float* lq2 = (const float*)d_in[7];
    const float* lk2 = (const float*)d_in[8];
    const float* lnw = (const float*)d_in[9];
    const float* lnb = (const float*)d_in[10];
    float* out = (float*)d_out;

    __nv_bfloat16 *xhi, *xlo, *whi, *wlo, *ahi, *alo;
    __nv_bfloat16 *qhi, *qlo, *khi, *klo, *vhi, *vlo;
    cudaGetSymbolAddress((void**)&xhi, g_xhi);
    cudaGetSymbolAddress((void**)&xlo, g_xlo);
    cudaGetSymbolAddress((void**)&whi, g_whi);
    cudaGetSymbolAddress((void**)&wlo, g_wlo);
    cudaGetSymbolAddress((void**)&ahi, g_ahi);
    cudaGetSymbolAddress((void**)&alo, g_alo);
    cudaGetSymbolAddress((void**)&qhi, g_Qhi);
    cudaGetSymbolAddress((void**)&qlo, g_Qlo);
    cudaGetSymbolAddress((void**)&khi, g_Khi);
    cudaGetSymbolAddress((void**)&klo, g_Klo);
    cudaGetSymbolAddress((void**)&vhi, g_Vhi);
    cudaGetSymbolAddress((void**)&vlo, g_Vlo);

    const int nx4 = (MROWS * D_EMB) / 4;
    const int nw4 = (D_EMB * D_EMB) / 4;

    // launches 1-4 (5th = QKV GEMM gets the ncu sample)
    split_kernel<<<(nx4 + 255) / 256, 256>>>(x, xhi, xlo, nx4);
    wsplit_kernel<<<(nw4 + 255) / 256, 256>>>(Wq, whi, wlo, 0, 1);
    wsplit_kernel<<<(nw4 + 255) / 256, 256>>>(Wk, whi, wlo, 2048, 0);
    wsplit_kernel<<<(nw4 + 255) / 256, 256>>>(Wv, whi, wlo, 4096, 0);

    cudaFuncSetAttribute(gemm_bf16x3<0>, cudaFuncAttributeMaxDynamicSharedMemorySize, G_SMEM);
    cudaFuncSetAttribute(gemm_bf16x3<1>, cudaFuncAttributeMaxDynamicSharedMemorySize, G_SMEM);

    // fused QKV projection + rope + split epilogue
    dim3 gqkv(NQKV / 256, MROWS / 128);   // (24, 32)
    gemm_bf16x3<1><<<gqkv, 512, G_SMEM>>>(xhi, xlo, whi, wlo, nullptr,
                                          MROWS, NQKV, D_EMB, WCOLS, 0);

    lam_kernel<<<1, 64>>>(lq1, lk1, lq2, lk2);

    cudaFuncSetAttribute(flash_mma_kernel, cudaFuncAttributeMaxDynamicSharedMemorySize, FL_SMEM);
    flash_mma_kernel<<<dim3(32, NHEAD, BATCH), 256, FL_SMEM>>>(
        qhi, qlo, khi, klo, vhi, vlo, lnw, lnb, ahi, alo);

    wsplit_kernel<<<(nw4 + 255) / 256, 256>>>(Wo, whi, wlo, 6144, 0);

    // output projection
    dim3 go(D_EMB / 256, MROWS / 128);    // (8, 32)
    gemm_bf16x3<0><<<go, 512, G_SMEM>>>(ahi, alo, whi + 6144, wlo + 6144, out,
                                        MROWS, D_EMB, D_EMB, WCOLS, D_EMB);
}

// round 8
// speedup vs baseline: 1.1674x; 1.0329x over previous
#include <cuda_runtime.h>
#include <cuda_bf16.h>
#include <cstdint>
#include <cstddef>

#define S_LEN 2048
#define D_EMB 2048
#define NHEAD 16
#define HDIM 64
#define DVDIM 128
#define BATCH 2
#define MROWS (BATCH * S_LEN)   // 4096
#define NQKV 6144
#define WCOLS 8192

#define LAMBDA_INIT_F 0.78360576653162435f
#define ONE_MINUS_LI_F 0.21639423346837565f
#define LN1E4_OVER_32 (9.210340371976184f / 32.0f)

// ---------------- scratch (device globals) -------------------------------
__device__ float g_lam;
__device__ float2 g_rope[S_LEN * 32];          // [s][j] -> (cos, sin)

__device__ __nv_bfloat16 g_xhi[(size_t)MROWS * D_EMB];
__device__ __nv_bfloat16 g_xlo[(size_t)MROWS * D_EMB];
__device__ __nv_bfloat16 g_whi[(size_t)D_EMB * WCOLS];   // [K, Wq|Wk|Wv|Wo]
__device__ __nv_bfloat16 g_wlo[(size_t)D_EMB * WCOLS];
__device__ __nv_bfloat16 g_ahi[(size_t)MROWS * D_EMB];
__device__ __nv_bfloat16 g_alo[(size_t)MROWS * D_EMB];

__device__ __nv_bfloat16 g_Qhi[(size_t)MROWS * D_EMB];
__device__ __nv_bfloat16 g_Qlo[(size_t)MROWS * D_EMB];
__device__ __nv_bfloat16 g_Khi[(size_t)MROWS * D_EMB];
__device__ __nv_bfloat16 g_Klo[(size_t)MROWS * D_EMB];
__device__ __nv_bfloat16 g_Vhi[(size_t)MROWS * D_EMB];
__device__ __nv_bfloat16 g_Vlo[(size_t)MROWS * D_EMB];

// ---------------- common PTX helpers --------------------------------------
__device__ __forceinline__ uint32_t smem_u32(const void* p) {
    return (uint32_t)__cvta_generic_to_shared(p);
}
__device__ __forceinline__ void cp16(uint32_t s, const void* g) {
    asm volatile("cp.async.ca.shared.global [%0], [%1], 16;" :: "r"(s), "l"(g));
}
__device__ __forceinline__ void cp16cg(uint32_t s, const void* g) {
    asm volatile("cp.async.cg.shared.global [%0], [%1], 16;" :: "r"(s), "l"(g));
}
__device__ __forceinline__ void ldmx4(uint32_t r[4], uint32_t addr) {
    asm volatile("ldmatrix.sync.aligned.m8n8.x4.shared.b16 {%0,%1,%2,%3}, [%4];"
        : "=r"(r[0]), "=r"(r[1]), "=r"(r[2]), "=r"(r[3]) : "r"(addr));
}
__device__ __forceinline__ void ldmx2t(uint32_t r[2], uint32_t addr) {
    asm volatile("ldmatrix.sync.aligned.m8n8.x2.trans.shared.b16 {%0,%1}, [%2];"
        : "=r"(r[0]), "=r"(r[1]) : "r"(addr));
}
__device__ __forceinline__ void ldmx4t(uint32_t r[4], uint32_t addr) {
    asm volatile("ldmatrix.sync.aligned.m8n8.x4.trans.shared.b16 {%0,%1,%2,%3}, [%4];"
        : "=r"(r[0]), "=r"(r[1]), "=r"(r[2]), "=r"(r[3]) : "r"(addr));
}
__device__ __forceinline__ void mma_bf16(float c[4], const uint32_t a[4], const uint32_t b[2]) {
    asm volatile("mma.sync.aligned.m16n8k16.row.col.f32.bf16.bf16.f32 "
        "{%0,%1,%2,%3}, {%4,%5,%6,%7}, {%8,%9}, {%0,%1,%2,%3};"
        : "+f"(c[0]), "+f"(c[1]), "+f"(c[2]), "+f"(c[3])
        : "r"(a[0]), "r"(a[1]), "r"(a[2]), "r"(a[3]), "r"(b[0]), "r"(b[1]));
}
__device__ __forceinline__ uint32_t pack_bf16(float lo, float hi) {
    uint32_t r;
    asm("cvt.rn.bf16x2.f32 %0, %1, %2;" : "=r"(r) : "f"(hi), "f"(lo));
    return r;
}
__device__ __forceinline__ float fexp(float x) {
    float t = fmaxf(x, -60.0f) * 1.44269504088896340736f;
    float fi = floorf(t);
    float f = t - fi;
    float p = 1.53964252399628e-4f;
    p = p * f + 1.33336498402e-3f;
    p = p * f + 9.61817668305e-3f;
    p = p * f + 5.55041086648e-2f;
    p = p * f + 2.40226506959101e-1f;
    p = p * f + 6.93147180559945e-1f;
    p = p * f + 1.0f;
    return __int_as_float(__float_as_int(p) + (((int)fi) << 23));
}
__device__ __forceinline__ void split2(float v0, float v1, uint32_t& hw, uint32_t& lw) {
    __nv_bfloat16 h0 = __float2bfloat16(v0);
    __nv_bfloat16 h1 = __float2bfloat16(v1);
    __nv_bfloat162 hh = __halves2bfloat162(h0, h1);
    hw = *(uint32_t*)&hh;
    lw = pack_bf16(v0 - __bfloat162float(h0), v1 - __bfloat162float(h1));
}

// =================== fp32 -> (bf16 hi, bf16 lo) split ====================
__global__ void split_kernel(const float* __restrict__ in,
                             __nv_bfloat16* __restrict__ hi,
                             __nv_bfloat16* __restrict__ lo, int n4)
{
    int i = blockIdx.x * blockDim.x + threadIdx.x;
    if (i >= n4) return;
    float4 v = ((const float4*)in)[i];
    uint32_t h0, l0, h1, l1;
    split2(v.x, v.y, h0, l0);
    split2(v.z, v.w, h1, l1);
    ((uint32_t*)hi)[2 * i]     = h0;
    ((uint32_t*)hi)[2 * i + 1] = h1;
    ((uint32_t*)lo)[2 * i]     = l0;
    ((uint32_t*)lo)[2 * i + 1] = l1;
}

// ===== all 4 W -> packed [2048, 8192] + split; also fills rope table =====
__global__ void wsplit_all_kernel(const float* __restrict__ W0, const float* __restrict__ W1,
                                  const float* __restrict__ W2, const float* __restrict__ W3,
                                  __nv_bfloat16* __restrict__ hi, __nv_bfloat16* __restrict__ lo)
{
    const int wsel = blockIdx.y;
    if (wsel == 0 && blockIdx.x < 256) {
        int idx = blockIdx.x * 256 + threadIdx.x;   // 65536 = 2048*32
        int s = idx >> 5, j = idx & 31;
        float inv = expf(-(float)j * LN1E4_OVER_32);
        float sn, cs;
        sincosf((float)s * inv, &sn, &cs);
        g_rope[idx] = make_float2(cs, sn);
    }
    int i = blockIdx.x * blockDim.x + threadIdx.x;
    if (i >= (D_EMB * D_EMB) / 4) return;
    const float* in = (wsel == 0) ? W0 : (wsel == 1) ? W1 : (wsel == 2) ? W2 : W3;
    int r = i >> 9;
    int c4 = (i & 511) << 2;
    float4 v = ((const float4*)in)[i];
    uint32_t h0, l0, h1, l1;
    split2(v.x, v.y, h0, l0);
    split2(v.z, v.w, h1, l1);
    size_t o = ((size_t)r * WCOLS + wsel * 2048 + c4) >> 1;
    ((uint32_t*)hi)[o]     = h0;
    ((uint32_t*)hi)[o + 1] = h1;
    ((uint32_t*)lo)[o]     = l0;
    ((uint32_t*)lo)[o + 1] = l1;
}

// =================== tensor-core GEMM (bf16 x3 split) ====================
// C[M,N] = A[M,K] * B[K,N]. 512 threads, 128x256 tile, BK=32, 3 stages,
// prefetch distance 2, ONE barrier per iteration.
#define GBK 32
#define GAP 80
#define GBP 528
#define GOFF_AL (128 * GAP)
#define GOFF_BH (2 * 128 * GAP)
#define GOFF_BL (GOFF_BH + GBK * GBP)
#define GSTAGE (GOFF_BL + GBK * GBP)
#define G_SMEM (3 * GSTAGE)

template <int MODE>
__global__ __launch_bounds__(512, 1)
void gemm_bf16x3(const __nv_bfloat16* __restrict__ Ahi, const __nv_bfloat16* __restrict__ Alo,
                 const __nv_bfloat16* __restrict__ Bhi, const __nv_bfloat16* __restrict__ Blo,
                 float* __restrict__ C, int M, int N, int K, int ldb, int ldc)
{
    extern __shared__ __align__(16) uint8_t gsm[];
    const uint32_t sbase = smem_u32(gsm);
    const int tid = threadIdx.x;
    const int lane = tid & 31;
    const int wid = tid >> 5;
    const int m0 = blockIdx.y * 128;
    const int n0 = blockIdx.x * 256;

    const int wm = wid & 3;
    const int wn = wid >> 2;

    const int KT = K / GBK;

    auto load_stage = [&](int t) {
        uint32_t st = sbase + (t % 3) * GSTAGE;
        int k0 = t * GBK;
#pragma unroll
        for (int j = 0; j < 6; j++) {
            int cid = tid + 512 * j;
            if (cid < 1024) {
                int hl = cid >> 9;
                int sub = cid & 511;
                int row = sub >> 2;
                int ch = sub & 3;
                const __nv_bfloat16* src = (hl ? Alo : Ahi)
                    + (size_t)(m0 + row) * K + k0 + ch * 8;
                cp16cg(st + (hl ? GOFF_AL : 0) + row * GAP + ch * 16, src);
            } else {
                int c2 = cid - 1024;
                int hl = c2 >> 10;
                int sub = c2 & 1023;
                int row = sub >> 5;
                int ch = sub & 31;
                const __nv_bfloat16* src = (hl ? Blo : Bhi)
                    + (size_t)(k0 + row) * ldb + n0 + ch * 8;
                cp16cg(st + (hl ? GOFF_BL : GOFF_BH) + row * GBP + ch * 16, src);
            }
        }
        asm volatile("cp.async.commit_group;");
    };

    load_stage(0);
    load_stage(1);

    float acc[2][8][4];
#pragma unroll
    for (int i = 0; i < 2; i++)
#pragma unroll
        for (int j = 0; j < 8; j++)
#pragma unroll
            for (int l = 0; l < 4; l++) acc[i][j][l] = 0.f;

    const uint32_t aoff = (uint32_t)(wm * 32 + (lane & 15)) * GAP + ((lane >> 4) & 1) * 16;
    const uint32_t boff = (uint32_t)(lane & 15) * GBP + (uint32_t)wn * 128
                        + ((lane >> 4) & 1) * 16;

    for (int t = 0; t < KT; t++) {
        if (t + 1 < KT) asm volatile("cp.async.wait_group 1;");
        else            asm volatile("cp.async.wait_group 0;");
        __syncthreads();
        // prefetch distance 2: writes buffer (t+2)%3, reads buffer t%3 — no collision
        if (t + 2 < KT) load_stage(t + 2);

        uint32_t st = sbase + (t % 3) * GSTAGE;
#pragma unroll
        for (int kk = 0; kk < 2; kk++) {
            uint32_t ah[2][4], al[2][4];
            ldmx4(ah[0], st + aoff + kk * 32);
            ldmx4(ah[1], st + aoff + 16 * GAP + kk * 32);
            ldmx4(al[0], st + GOFF_AL + aoff + kk * 32);
            ldmx4(al[1], st + GOFF_AL + aoff + 16 * GAP + kk * 32);
            uint32_t bb = st + boff + (uint32_t)kk * 16 * GBP;
#pragma unroll
            for (int half = 0; half < 2; half++) {
                uint32_t bh[8], bl[8];
                ldmx4t(&bh[0], bb + GOFF_BH + half * 64);
                ldmx4t(&bh[4], bb + GOFF_BH + half * 64 + 32);
                ldmx4t(&bl[0], bb + GOFF_BL + half * 64);
                ldmx4t(&bl[4], bb + GOFF_BL + half * 64 + 32);
#pragma unroll
                for (int mt = 0; mt < 2; mt++)
#pragma unroll
                    for (int nt = 0; nt < 4; nt++) {
                        int ng = half * 4 + nt;
                        mma_bf16(acc[mt][ng], ah[mt], &bh[nt * 2]);
                        mma_bf16(acc[mt][ng], al[mt], &bh[nt * 2]);
                        mma_bf16(acc[mt][ng], ah[mt], &bl[nt * 2]);
                    }
            }
        }
    }

    // epilogue
    const int gid = lane >> 2, tig = lane & 3;
    if (MODE == 0) {
#pragma unroll
        for (int mt = 0; mt < 2; mt++) {
            int row = m0 + wm * 32 + mt * 16 + gid;
#pragma unroll
            for (int nt = 0; nt < 8; nt++) {
                int col = n0 + wn * 64 + nt * 8 + 2 * tig;
                *(float2*)&C[(size_t)row * ldc + col] = make_float2(acc[mt][nt][0], acc[mt][nt][1]);
                *(float2*)&C[(size_t)(row + 8) * ldc + col] = make_float2(acc[mt][nt][2], acc[mt][nt][3]);
            }
        }
    } else {
        const int region = n0 >> 11;    // 0=Q, 1=K, 2=V
        __nv_bfloat16* dh = (region == 0) ? g_Qhi : (region == 1) ? g_Khi : g_Vhi;
        __nv_bfloat16* dl = (region == 0) ? g_Qlo : (region == 1) ? g_Klo : g_Vlo;
#pragma unroll
        for (int mt = 0; mt < 2; mt++) {
#pragma unroll
            for (int nt = 0; nt < 8; nt++) {
                int col = n0 + wn * 64 + nt * 8 + 2 * tig;
                int cl = col & 2047;
                int j = (cl & 63) >> 1;
#pragma unroll
                for (int rr = 0; rr < 2; rr++) {
                    int row = m0 + wm * 32 + mt * 16 + gid + rr * 8;
                    float v0 = acc[mt][nt][rr * 2 + 0];
                    float v1 = acc[mt][nt][rr * 2 + 1];
                    if (region < 2) {
                        int s = row & (S_LEN - 1);
                        float2 t = g_rope[(s << 5) + j];
                        float f0 = v0 * t.x - v1 * t.y;
                        float f1 = v1 * t.x + v0 * t.y;
                        v0 = f0; v1 = f1;
                    }
                    uint32_t hw, lw;
                    split2(v0, v1, hw, lw);
                    size_t o = ((size_t)row * D_EMB + cl) >> 1;
                    ((uint32_t*)dh)[o] = hw;
                    ((uint32_t*)dl)[o] = lw;
                }
            }
        }
    }
}

// ---------------- lambda scalar ------------------------------------------
__global__ void lam_kernel(const float* __restrict__ lq1, const float* __restrict__ lk1,
                           const float* __restrict__ lq2, const float* __restrict__ lk2)
{
    __shared__ float s1[64], s2[64];
    int t = threadIdx.x;
    s1[t] = lq1[t] * lk1[t];
    s2[t] = lq2[t] * lk2[t];
    __syncthreads();
    if (t == 0) {
        float d1 = 0.f, d2 = 0.f;
        for (int i = 0; i < 64; i++) { d1 += s1[i]; d2 += s2[i]; }
        g_lam = expf(d1) - expf(d2) + LAMBDA_INIT_F;
    }
}

// ================= MMA dual-branch flash attention (double-buffered) ======
#define PQB 144
#define PVB 272
#define QK_TILE (64 * PQB)              // 9216
#define V_TILE  (64 * PVB)              // 17408
#define FOFF_Q 0
#define FSTG (4 * QK_TILE + 2 * V_TILE) // 71680
#define FOFF_S0 (4 * QK_TILE)           // 36864
#define FL_SMEM (FOFF_S0 + 2 * FSTG)    // 180224

__global__ __launch_bounds__(256, 1)
void flash_mma_kernel(const __nv_bfloat16* __restrict__ Qhi, const __nv_bfloat16* __restrict__ Qlo,
                      const __nv_bfloat16* __restrict__ Khi, const __nv_bfloat16* __restrict__ Klo,
                      const __nv_bfloat16* __restrict__ Vhi, const __nv_bfloat16* __restrict__ Vlo,
                      const float* __restrict__ lnw, const float* __restrict__ lnb,
                      __nv_bfloat16* __restrict__ Ahi, __nv_bfloat16* __restrict__ Alo)
{
    extern __shared__ __align__(16) uint8_t smraw[];
    const uint32_t sbase = smem_u32(smraw);
    float* sOut = (float*)smraw;

    const int tid = threadIdx.x;
    const int lane = tid & 31;
    const int wid = tid >> 5;
    const int br = wid >> 2;
    const int rbase = (wid & 3) * 16;
    const int g = lane >> 2;
    const int tg = lane & 3;

    const int qt = (int)gridDim.x - 1 - (int)blockIdx.x;
    const int h = blockIdx.y;
    const int b = blockIdx.z;
    const int q0t = qt * 64;
    const size_t rowBase = (size_t)b * S_LEN;
    const int colH = h * 128;

    // ---- Q tiles ----
#pragma unroll
    for (int it = 0; it < 8; it++) {
        int idx = tid + 256 * it;
        int ch = idx & 7, r = (idx >> 3) & 63, t = idx >> 9;
        const __nv_bfloat16* src = ((t & 1) ? Qlo : Qhi)
            + (rowBase + q0t + r) * D_EMB + colH + (t >> 1) * 64 + ch * 8;
        cp16(sbase + FOFF_Q + t * QK_TILE + r * PQB + ch * 16, src);
    }
    asm volatile("cp.async.commit_group;");
    asm volatile("cp.async.wait_group 0;");
    __syncthreads();

    uint32_t qh[4][4], ql[4][4];
    {
        uint32_t qoff = (uint32_t)(rbase + (lane & 15)) * PQB + ((lane >> 4) << 4);
        uint32_t bh_ = sbase + FOFF_Q + (br * 2) * QK_TILE;
#pragma unroll
        for (int s = 0; s < 4; s++) {
            ldmx4(qh[s], bh_ + qoff + s * 32);
            ldmx4(ql[s], bh_ + QK_TILE + qoff + s * 32);
        }
    }

    auto load_kv = [&](int kt) {
        uint32_t stb = sbase + FOFF_S0 + (kt & 1) * FSTG;
#pragma unroll
        for (int it = 0; it < 8; it++) {
            int idx = tid + 256 * it;
            int ch = idx & 7, r = (idx >> 3) & 63, t = idx >> 9;
            const __nv_bfloat16* src = ((t & 1) ? Klo : Khi)
                + (rowBase + (size_t)kt * 64 + r) * D_EMB + colH + (t >> 1) * 64 + ch * 8;
            cp16(stb + t * QK_TILE + r * PQB + ch * 16, src);
        }
#pragma unroll
        for (int it = 0; it < 8; it++) {
            int idx = tid + 256 * it;
            int ch = idx & 15, r = (idx >> 4) & 63, t = idx >> 10;
            const __nv_bfloat16* src = (t ? Vlo : Vhi)
                + (rowBase + (size_t)kt * 64 + r) * D_EMB + colH + ch * 8;
            cp16(stb + 4 * QK_TILE + t * V_TILE + r * PVB + ch * 16, src);
        }
        asm volatile("cp.async.commit_group;");
    };

    float o[16][4];
#pragma unroll
    for (int i = 0; i < 16; i++)
#pragma unroll
        for (int j = 0; j < 4; j++) o[i][j] = 0.f;
    float m_a = -1e30f, m_b = -1e30f, l_a = 0.f, l_b = 0.f;

    load_kv(0);

    for (int kt = 0; kt <= qt; kt++) {
        if (kt < qt) {
            load_kv(kt + 1);
            asm volatile("cp.async.wait_group 1;");
        } else {
            asm volatile("cp.async.wait_group 0;");
        }
        __syncthreads();

        const uint32_t stb = sbase + FOFF_S0 + (kt & 1) * FSTG;

        float sc[8][4];
#pragma unroll
        for (int i = 0; i < 8; i++)
#pragma unroll
            for (int j = 0; j < 4; j++) sc[i][j] = 0.f;

        const uint32_t kbh = stb + (br * 2) * QK_TILE;
        const uint32_t koff = (uint32_t)(lane & 7) * PQB + ((lane >> 3) << 4);
#pragma unroll
        for (int nt = 0; nt < 8; nt++) {
            uint32_t a = koff + (uint32_t)nt * 8 * PQB;
            uint32_t kh0[4], kh1[4], kl0[4], kl1[4];
            ldmx4(kh0, kbh + a);
            ldmx4(kh1, kbh + a + 64);
            ldmx4(kl0, kbh + QK_TILE + a);
            ldmx4(kl1, kbh + QK_TILE + a + 64);
            mma_bf16(sc[nt], qh[0], &kh0[0]);
            mma_bf16(sc[nt], ql[0], &kh0[0]);
            mma_bf16(sc[nt], qh[0], &kl0[0]);
            mma_bf16(sc[nt], qh[1], &kh0[2]);
            mma_bf16(sc[nt], ql[1], &kh0[2]);
            mma_bf16(sc[nt], qh[1], &kl0[2]);
            mma_bf16(sc[nt], qh[2], &kh1[0]);
            mma_bf16(sc[nt], ql[2], &kh1[0]);
            mma_bf16(sc[nt], qh[2], &kl1[0]);
            mma_bf16(sc[nt], qh[3], &kh1[2]);
            mma_bf16(sc[nt], ql[3], &kh1[2]);
            mma_bf16(sc[nt], qh[3], &kl1[2]);
        }

        const bool diag = (kt == qt);
        float mxa = -1e30f, mxb = -1e30f;
#pragma unroll
        for (int nt = 0; nt < 8; nt++) {
            int c0 = nt * 8 + 2 * tg;
#pragma unroll
            for (int e = 0; e < 4; e++) {
                int row = rbase + g + ((e >> 1) << 3);
                int col = c0 + (e & 1);
                float v = sc[nt][e] * 0.125f;
                if (diag && col > row) v = -1e30f;
                sc[nt][e] = v;
            }
            mxa = fmaxf(mxa, fmaxf(sc[nt][0], sc[nt][1]));
            mxb = fmaxf(mxb, fmaxf(sc[nt][2], sc[nt][3]));
        }
        mxa = fmaxf(mxa, __shfl_xor_sync(0xffffffffu, mxa, 1));
        mxa = fmaxf(mxa, __shfl_xor_sync(0xffffffffu, mxa, 2));
        mxb = fmaxf(mxb, __shfl_xor_sync(0xffffffffu, mxb, 1));
        mxb = fmaxf(mxb, __shfl_xor_sync(0xffffffffu, mxb, 2));
        float mna = fmaxf(m_a, mxa), mnb = fmaxf(m_b, mxb);
        float alf_a = fexp(m_a - mna), alf_b = fexp(m_b - mnb);
        m_a = mna; m_b = mnb;

        float suma = 0.f, sumb = 0.f;
        uint32_t ph[4][4], pl[4][4];
#pragma unroll
        for (int s2 = 0; s2 < 4; s2++) {
#pragma unroll
            for (int hf = 0; hf < 2; hf++) {
                int nt = 2 * s2 + hf;
                float p0 = fexp(sc[nt][0] - m_a);
                float p1 = fexp(sc[nt][1] - m_a);
                float p2 = fexp(sc[nt][2] - m_b);
                float p3 = fexp(sc[nt][3] - m_b);
                suma += p0 + p1; sumb += p2 + p3;
                __nv_bfloat16 h0 = __float2bfloat16(p0);
                __nv_bfloat16 h1 = __float2bfloat16(p1);
                __nv_bfloat16 h2 = __float2bfloat16(p2);
                __nv_bfloat16 h3 = __float2bfloat16(p3);
                __nv_bfloat162 t01 = __halves2bfloat162(h0, h1);
                __nv_bfloat162 t23 = __halves2bfloat162(h2, h3);
                ph[s2][hf * 2 + 0] = *(uint32_t*)&t01;
                ph[s2][hf * 2 + 1] = *(uint32_t*)&t23;
                pl[s2][hf * 2 + 0] = pack_bf16(p0 - __bfloat162float(h0),
                                               p1 - __bfloat162float(h1));
                pl[s2][hf * 2 + 1] = pack_bf16(p2 - __bfloat162float(h2),
                                               p3 - __bfloat162float(h3));
            }
        }
        suma += __shfl_xor_sync(0xffffffffu, suma, 1);
        suma += __shfl_xor_sync(0xffffffffu, suma, 2);
        sumb += __shfl_xor_sync(0xffffffffu, sumb, 1);
        sumb += __shfl_xor_sync(0xffffffffu, sumb, 2);
        l_a = alf_a * l_a + suma;
        l_b = alf_b * l_b + sumb;

#pragma unroll
        for (int vt = 0; vt < 16; vt++) {
            o[vt][0] *= alf_a; o[vt][1] *= alf_a;
            o[vt][2] *= alf_b; o[vt][3] *= alf_b;
        }

        // ---- O += P V : ldmatrix.x4.trans fetches 2 column fragments ----
        const uint32_t vb = stb + 4 * QK_TILE;
        const uint32_t vrow4 = (uint32_t)(lane & 15) * PVB + ((lane >> 4) << 4);
#pragma unroll
        for (int vt2 = 0; vt2 < 8; vt2++) {
#pragma unroll
            for (int s2 = 0; s2 < 4; s2++) {
                uint32_t addr = (uint32_t)(s2 * 16) * PVB + vrow4 + vt2 * 32;
                uint32_t bh4[4], bl4[4];
                ldmx4t(bh4, vb + addr);
                ldmx4t(bl4, vb + V_TILE + addr);
                mma_bf16(o[2 * vt2],     ph[s2], &bh4[0]);
                mma_bf16(o[2 * vt2],     pl[s2], &bh4[0]);
                mma_bf16(o[2 * vt2],     ph[s2], &bl4[0]);
                mma_bf16(o[2 * vt2 + 1], ph[s2], &bh4[2]);
                mma_bf16(o[2 * vt2 + 1], pl[s2], &bh4[2]);
                mma_bf16(o[2 * vt2 + 1], ph[s2], &bl4[2]);
            }
        }
        __syncthreads();
    }

    float lam = g_lam;
    float ra = 1.0f / l_a, rb = 1.0f / l_b;

    if (br == 0) {
#pragma unroll
        for (int vt = 0; vt < 16; vt++) {
            int c = vt * 8 + 2 * tg;
            *(float2*)&sOut[(rbase + g) * 128 + c] = make_float2(o[vt][0] * ra, o[vt][1] * ra);
            *(float2*)&sOut[(rbase + g + 8) * 128 + c] = make_float2(o[vt][2] * rb, o[vt][3] * rb);
        }
    }
    __syncthreads();
    if (br == 1) {
#pragma unroll
        for (int vt = 0; vt < 16; vt++) {
            int c = vt * 8 + 2 * tg;
            float2* p0 = (float2*)&sOut[(rbase + g) * 128 + c];
            float2 v0 = *p0;
            v0.x -= lam * o[vt][0] * ra; v0.y -= lam * o[vt][1] * ra;
            *p0 = v0;
            float2* p1 = (float2*)&sOut[(rbase + g + 8) * 128 + c];
            float2 v1 = *p1;
            v1.x -= lam * o[vt][2] * rb; v1.y -= lam * o[vt][3] * rb;
            *p1 = v1;
        }
    }
    __syncthreads();

    // ---- RMSNorm + scale + split bf16 write ----
    {
        int r = tid >> 2;
        int q4 = tid & 3;
        float ss = 0.f;
#pragma unroll
        for (int u = 0; u < 32; u++) {
            float v = sOut[r * 128 + q4 * 32 + u];
            ss += v * v;
        }
        ss += __shfl_xor_sync(0xffffffffu, ss, 1);
        ss += __shfl_xor_sync(0xffffffffu, ss, 2);
        float rn = rsqrtf(ss * (1.0f / 128.0f) + 1e-8f);
        size_t outrow = (rowBase + q0t + r) * D_EMB + colH;
#pragma unroll
        for (int u = 0; u < 32; u += 2) {
            int e = q4 * 32 + u;
            float v0 = (sOut[r * 128 + e] * rn * lnw[e] + lnb[e]) * ONE_MINUS_LI_F;
            float v1 = (sOut[r * 128 + e + 1] * rn * lnw[e + 1] + lnb[e + 1]) * ONE_MINUS_LI_F;
            uint32_t hw, lw;
            split2(v0, v1, hw, lw);
            *(uint32_t*)&Ahi[outrow + e] = hw;
            *(uint32_t*)&Alo[outrow + e] = lw;
        }
    }
}

// ---------------- launch ---------------------------------------------------
extern "C" void kernel_launch(void* const* d_in, const int* in_sizes, int n_in,
                              void* d_out, int out_size)
{
    (void)in_sizes; (void)n_in; (void)out_size;
    const float* x   = (const float*)d_in[0];
    const float* Wq  = (const float*)d_in[1];
    const float* Wk  = (const float*)d_in[2];
    const float* Wv  = (const float*)d_in[3];
    const float* Wo  = (const float*)d_in[4];
    const float* lq1 = (const float*)d_in[5];
    const float* lk1 = (const float*)d_in[6];
    const float* lq2 = (const float*)d_in[7];
    const float* lk2 = (const float*)d_in[8];
    const float* lnw = (const float*)d_in[9];
    const float* lnb = (const float*)d_in[10];
    float* out = (float*)d_out;

    __nv_bfloat16 *xhi, *xlo, *whi, *wlo, *ahi, *alo;
    __nv_bfloat16 *qhi, *qlo, *khi, *klo, *vhi, *vlo;
    cudaGetSymbolAddress((void**)&xhi, g_xhi);
    cudaGetSymbolAddress((void**)&xlo, g_xlo);
    cudaGetSymbolAddress((void**)&whi, g_whi);
    cudaGetSymbolAddress((void**)&wlo, g_wlo);
    cudaGetSymbolAddress((void**)&ahi, g_ahi);
    cudaGetSymbolAddress((void**)&alo, g_alo);
    cudaGetSymbolAddress((void**)&qhi, g_Qhi);
    cudaGetSymbolAddress((void**)&qlo, g_Qlo);
    cudaGetSymbolAddress((void**)&khi, g_Khi);
    cudaGetSymbolAddress((void**)&klo, g_Klo);
    cudaGetSymbolAddress((void**)&vhi, g_Vhi);
    cudaGetSymbolAddress((void**)&vlo, g_Vlo);

    const int nx4 = (MROWS * D_EMB) / 4;
    const int nw4 = (D_EMB * D_EMB) / 4;

    dim3 wsg((nw4 + 255) / 256, 4);
    wsplit_all_kernel<<<wsg, 256>>>(Wq, Wk, Wv, Wo, whi, wlo);
    split_kernel<<<(nx4 + 255) / 256, 256>>>(x, xhi, xlo, nx4);

    cudaFuncSetAttribute(gemm_bf16x3<0>, cudaFuncAttributeMaxDynamicSharedMemorySize, G_SMEM);
    cudaFuncSetAttribute(gemm_bf16x3<1>, cudaFuncAttributeMaxDynamicSharedMemorySize, G_SMEM);

    // fused QKV projection + rope + split epilogue
    dim3 gqkv(NQKV / 256, MROWS / 128);   // (24, 32)
    gemm_bf16x3<1><<<gqkv, 512, G_SMEM>>>(xhi, xlo, whi, wlo, nullptr,
                                          MROWS, NQKV, D_EMB, WCOLS, 0);

    lam_kernel<<<1, 64>>>(lq1, lk1, lq2, lk2);

    cudaFuncSetAttribute(flash_mma_kernel, cudaFuncAttributeMaxDynamicSharedMemorySize, FL_SMEM);
    flash_mma_kernel<<<dim3(32, NHEAD, BATCH), 256, FL_SMEM>>>(
        qhi, qlo, khi, klo, vhi, vlo, lnw, lnb, ahi, alo);

    // output projection
    dim3 go(D_EMB / 256, MROWS / 128);    // (8, 32)
    gemm_bf16x3<0><<<go, 512, G_SMEM>>>(ahi, alo, whi + 6144, wlo + 6144, out,
                                        MROWS, D_EMB, D_EMB, WCOLS, D_EMB);
}

// round 9
// speedup vs baseline: 1.2530x; 1.0733x over previous
#include <cuda_runtime.h>
#include <cuda_bf16.h>
#include <cstdint>
#include <cstddef>

#define S_LEN 2048
#define D_EMB 2048
#define NHEAD 16
#define HDIM 64
#define DVDIM 128
#define BATCH 2
#define MROWS (BATCH * S_LEN)   // 4096
#define NQKV 6144
#define WCOLS 8192

#define LAMBDA_INIT_F 0.78360576653162435f
#define ONE_MINUS_LI_F 0.21639423346837565f
#define LN1E4_OVER_32 (9.210340371976184f / 32.0f)

// ---------------- scratch (device globals) -------------------------------
__device__ float2 g_rope[S_LEN * 32];          // [s][j] -> (cos, sin)

__device__ __nv_bfloat16 g_xhi[(size_t)MROWS * D_EMB];
__device__ __nv_bfloat16 g_xlo[(size_t)MROWS * D_EMB];
__device__ __nv_bfloat16 g_whi[(size_t)D_EMB * WCOLS];   // [K, Wq|Wk|Wv|Wo]
__device__ __nv_bfloat16 g_wlo[(size_t)D_EMB * WCOLS];
__device__ __nv_bfloat16 g_ahi[(size_t)MROWS * D_EMB];
__device__ __nv_bfloat16 g_alo[(size_t)MROWS * D_EMB];

__device__ __nv_bfloat16 g_Qhi[(size_t)MROWS * D_EMB];
__device__ __nv_bfloat16 g_Qlo[(size_t)MROWS * D_EMB];
__device__ __nv_bfloat16 g_Khi[(size_t)MROWS * D_EMB];
__device__ __nv_bfloat16 g_Klo[(size_t)MROWS * D_EMB];
__device__ __nv_bfloat16 g_Vhi[(size_t)MROWS * D_EMB];
__device__ __nv_bfloat16 g_Vlo[(size_t)MROWS * D_EMB];

// ---------------- common PTX helpers --------------------------------------
__device__ __forceinline__ uint32_t smem_u32(const void* p) {
    return (uint32_t)__cvta_generic_to_shared(p);
}
__device__ __forceinline__ void cp16(uint32_t s, const void* g) {
    asm volatile("cp.async.ca.shared.global [%0], [%1], 16;" :: "r"(s), "l"(g));
}
__device__ __forceinline__ void cp16cg(uint32_t s, const void* g) {
    asm volatile("cp.async.cg.shared.global [%0], [%1], 16;" :: "r"(s), "l"(g));
}
__device__ __forceinline__ void ldmx4(uint32_t r[4], uint32_t addr) {
    asm volatile("ldmatrix.sync.aligned.m8n8.x4.shared.b16 {%0,%1,%2,%3}, [%4];"
        : "=r"(r[0]), "=r"(r[1]), "=r"(r[2]), "=r"(r[3]) : "r"(addr));
}
__device__ __forceinline__ void ldmx4t(uint32_t r[4], uint32_t addr) {
    asm volatile("ldmatrix.sync.aligned.m8n8.x4.trans.shared.b16 {%0,%1,%2,%3}, [%4];"
        : "=r"(r[0]), "=r"(r[1]), "=r"(r[2]), "=r"(r[3]) : "r"(addr));
}
__device__ __forceinline__ void mma_bf16(float c[4], const uint32_t a[4], const uint32_t b[2]) {
    asm volatile("mma.sync.aligned.m16n8k16.row.col.f32.bf16.bf16.f32 "
        "{%0,%1,%2,%3}, {%4,%5,%6,%7}, {%8,%9}, {%0,%1,%2,%3};"
        : "+f"(c[0]), "+f"(c[1]), "+f"(c[2]), "+f"(c[3])
        : "r"(a[0]), "r"(a[1]), "r"(a[2]), "r"(a[3]), "r"(b[0]), "r"(b[1]));
}
__device__ __forceinline__ uint32_t pack_bf16(float lo, float hi) {
    uint32_t r;
    asm("cvt.rn.bf16x2.f32 %0, %1, %2;" : "=r"(r) : "f"(hi), "f"(lo));
    return r;
}
__device__ __forceinline__ float fexp(float x) {
    float t = fmaxf(x, -60.0f) * 1.44269504088896340736f;
    float fi = floorf(t);
    float f = t - fi;
    float p = 1.53964252399628e-4f;
    p = p * f + 1.33336498402e-3f;
    p = p * f + 9.61817668305e-3f;
    p = p * f + 5.55041086648e-2f;
    p = p * f + 2.40226506959101e-1f;
    p = p * f + 6.93147180559945e-1f;
    p = p * f + 1.0f;
    return __int_as_float(__float_as_int(p) + (((int)fi) << 23));
}
__device__ __forceinline__ void split2(float v0, float v1, uint32_t& hw, uint32_t& lw) {
    __nv_bfloat16 h0 = __float2bfloat16(v0);
    __nv_bfloat16 h1 = __float2bfloat16(v1);
    __nv_bfloat162 hh = __halves2bfloat162(h0, h1);
    hw = *(uint32_t*)&hh;
    lw = pack_bf16(v0 - __bfloat162float(h0), v1 - __bfloat162float(h1));
}

// =================== fp32 -> (bf16 hi, bf16 lo) split ====================
__global__ void split_kernel(const float* __restrict__ in,
                             __nv_bfloat16* __restrict__ hi,
                             __nv_bfloat16* __restrict__ lo, int n4)
{
    int i = blockIdx.x * blockDim.x + threadIdx.x;
    if (i >= n4) return;
    float4 v = ((const float4*)in)[i];
    uint32_t h0, l0, h1, l1;
    split2(v.x, v.y, h0, l0);
    split2(v.z, v.w, h1, l1);
    ((uint32_t*)hi)[2 * i]     = h0;
    ((uint32_t*)hi)[2 * i + 1] = h1;
    ((uint32_t*)lo)[2 * i]     = l0;
    ((uint32_t*)lo)[2 * i + 1] = l1;
}

// ===== all 4 W -> packed [2048, 8192] + split; also fills rope table =====
__global__ void wsplit_all_kernel(const float* __restrict__ W0, const float* __restrict__ W1,
                                  const float* __restrict__ W2, const float* __restrict__ W3,
                                  __nv_bfloat16* __restrict__ hi, __nv_bfloat16* __restrict__ lo)
{
    const int wsel = blockIdx.y;
    if (wsel == 0 && blockIdx.x < 256) {
        int idx = blockIdx.x * 256 + threadIdx.x;
        int s = idx >> 5, j = idx & 31;
        float inv = expf(-(float)j * LN1E4_OVER_32);
        float sn, cs;
        sincosf((float)s * inv, &sn, &cs);
        g_rope[idx] = make_float2(cs, sn);
    }
    int i = blockIdx.x * blockDim.x + threadIdx.x;
    if (i >= (D_EMB * D_EMB) / 4) return;
    const float* in = (wsel == 0) ? W0 : (wsel == 1) ? W1 : (wsel == 2) ? W2 : W3;
    int r = i >> 9;
    int c4 = (i & 511) << 2;
    float4 v = ((const float4*)in)[i];
    uint32_t h0, l0, h1, l1;
    split2(v.x, v.y, h0, l0);
    split2(v.z, v.w, h1, l1);
    size_t o = ((size_t)r * WCOLS + wsel * 2048 + c4) >> 1;
    ((uint32_t*)hi)[o]     = h0;
    ((uint32_t*)hi)[o + 1] = h1;
    ((uint32_t*)lo)[o]     = l0;
    ((uint32_t*)lo)[o + 1] = l1;
}

// =================== tensor-core GEMM (bf16 x3 split) ====================
// C[M,N] = A[M,K] * B[K,N]. 256 threads, 128x128 tile, BK=32, 3 stages,
// prefetch distance 2, 1 barrier/iter, 2 CTAs per SM.
#define GBK 32
#define GAP 80                                // A pitch (32 bf16 + 16B pad)
#define GBP 272                               // B pitch (128 bf16 + 16B pad)
#define GOFF_AL (128 * GAP)                   // 10240
#define GOFF_BH (2 * 128 * GAP)               // 20480
#define GOFF_BL (GOFF_BH + GBK * GBP)         // 29184
#define GSTAGE (GOFF_BL + GBK * GBP)          // 37888
#define G_SMEM (3 * GSTAGE)                   // 113664

template <int MODE>
__global__ __launch_bounds__(256, 2)
void gemm_bf16x3(const __nv_bfloat16* __restrict__ Ahi, const __nv_bfloat16* __restrict__ Alo,
                 const __nv_bfloat16* __restrict__ Bhi, const __nv_bfloat16* __restrict__ Blo,
                 float* __restrict__ C, int M, int N, int K, int ldb, int ldc)
{
    extern __shared__ __align__(16) uint8_t gsm[];
    const uint32_t sbase = smem_u32(gsm);
    const int tid = threadIdx.x;
    const int lane = tid & 31;
    const int wid = tid >> 5;
    const int m0 = blockIdx.y * 128;
    const int n0 = blockIdx.x * 128;

    const int wm = wid & 3;      // 4 m-tiles of 32 rows
    const int wn = wid >> 2;     // 2 n-slabs of 64 cols

    const int KT = K / GBK;

    // per-stage: A 1024 chunks (128r x 4ch x 2hl), B 1024 (32r x 16ch x 2hl)
    auto load_stage = [&](int t) {
        uint32_t st = sbase + (t % 3) * GSTAGE;
        int k0 = t * GBK;
#pragma unroll
        for (int j = 0; j < 8; j++) {
            int cid = tid + 256 * j;
            if (cid < 1024) {
                int hl = cid >> 9;
                int sub = cid & 511;
                int row = sub >> 2;
                int ch = sub & 3;
                const __nv_bfloat16* src = (hl ? Alo : Ahi)
                    + (size_t)(m0 + row) * K + k0 + ch * 8;
                cp16cg(st + (hl ? GOFF_AL : 0) + row * GAP + ch * 16, src);
            } else {
                int c2 = cid - 1024;
                int hl = c2 >> 9;
                int sub = c2 & 511;
                int row = sub >> 4;
                int ch = sub & 15;
                const __nv_bfloat16* src = (hl ? Blo : Bhi)
                    + (size_t)(k0 + row) * ldb + n0 + ch * 8;
                cp16cg(st + (hl ? GOFF_BL : GOFF_BH) + row * GBP + ch * 16, src);
            }
        }
        asm volatile("cp.async.commit_group;");
    };

    load_stage(0);
    load_stage(1);

    float acc[2][8][4];
#pragma unroll
    for (int i = 0; i < 2; i++)
#pragma unroll
        for (int j = 0; j < 8; j++)
#pragma unroll
            for (int l = 0; l < 4; l++) acc[i][j][l] = 0.f;

    const uint32_t aoff = (uint32_t)(wm * 32 + (lane & 15)) * GAP + ((lane >> 4) & 1) * 16;
    const uint32_t boff = (uint32_t)(lane & 15) * GBP + (uint32_t)wn * 128
                        + ((lane >> 4) & 1) * 16;

    for (int t = 0; t < KT; t++) {
        if (t + 1 < KT) asm volatile("cp.async.wait_group 1;");
        else            asm volatile("cp.async.wait_group 0;");
        __syncthreads();
        if (t + 2 < KT) load_stage(t + 2);

        uint32_t st = sbase + (t % 3) * GSTAGE;
#pragma unroll
        for (int kk = 0; kk < 2; kk++) {
            uint32_t ah[2][4], al[2][4];
            ldmx4(ah[0], st + aoff + kk * 32);
            ldmx4(ah[1], st + aoff + 16 * GAP + kk * 32);
            ldmx4(al[0], st + GOFF_AL + aoff + kk * 32);
            ldmx4(al[1], st + GOFF_AL + aoff + 16 * GAP + kk * 32);
            uint32_t bb = st + boff + (uint32_t)kk * 16 * GBP;
#pragma unroll
            for (int half = 0; half < 2; half++) {
                uint32_t bh[8], bl[8];
                ldmx4t(&bh[0], bb + GOFF_BH + half * 64);
                ldmx4t(&bh[4], bb + GOFF_BH + half * 64 + 32);
                ldmx4t(&bl[0], bb + GOFF_BL + half * 64);
                ldmx4t(&bl[4], bb + GOFF_BL + half * 64 + 32);
#pragma unroll
                for (int mt = 0; mt < 2; mt++)
#pragma unroll
                    for (int nt = 0; nt < 4; nt++) {
                        int ng = half * 4 + nt;
                        mma_bf16(acc[mt][ng], ah[mt], &bh[nt * 2]);
                        mma_bf16(acc[mt][ng], al[mt], &bh[nt * 2]);
                        mma_bf16(acc[mt][ng], ah[mt], &bl[nt * 2]);
                    }
            }
        }
    }

    // epilogue
    const int gid = lane >> 2, tig = lane & 3;
    if (MODE == 0) {
#pragma unroll
        for (int mt = 0; mt < 2; mt++) {
            int row = m0 + wm * 32 + mt * 16 + gid;
#pragma unroll
            for (int nt = 0; nt < 8; nt++) {
                int col = n0 + wn * 64 + nt * 8 + 2 * tig;
                *(float2*)&C[(size_t)row * ldc + col] = make_float2(acc[mt][nt][0], acc[mt][nt][1]);
                *(float2*)&C[(size_t)(row + 8) * ldc + col] = make_float2(acc[mt][nt][2], acc[mt][nt][3]);
            }
        }
    } else {
        const int region = n0 >> 11;    // 0=Q, 1=K, 2=V
        __nv_bfloat16* dh = (region == 0) ? g_Qhi : (region == 1) ? g_Khi : g_Vhi;
        __nv_bfloat16* dl = (region == 0) ? g_Qlo : (region == 1) ? g_Klo : g_Vlo;
#pragma unroll
        for (int mt = 0; mt < 2; mt++) {
#pragma unroll
            for (int nt = 0; nt < 8; nt++) {
                int col = n0 + wn * 64 + nt * 8 + 2 * tig;
                int cl = col & 2047;
                int j = (cl & 63) >> 1;
#pragma unroll
                for (int rr = 0; rr < 2; rr++) {
                    int row = m0 + wm * 32 + mt * 16 + gid + rr * 8;
                    float v0 = acc[mt][nt][rr * 2 + 0];
                    float v1 = acc[mt][nt][rr * 2 + 1];
                    if (region < 2) {
                        int s = row & (S_LEN - 1);
                        float2 t = g_rope[(s << 5) + j];
                        float f0 = v0 * t.x - v1 * t.y;
                        float f1 = v1 * t.x + v0 * t.y;
                        v0 = f0; v1 = f1;
                    }
                    uint32_t hw, lw;
                    split2(v0, v1, hw, lw);
                    size_t o = ((size_t)row * D_EMB + cl) >> 1;
                    ((uint32_t*)dh)[o] = hw;
                    ((uint32_t*)dl)[o] = lw;
                }
            }
        }
    }
}

// ================= MMA dual-branch flash attention (double-buffered) ======
#define PQB 144
#define PVB 272
#define QK_TILE (64 * PQB)              // 9216
#define V_TILE  (64 * PVB)              // 17408
#define FOFF_Q 0
#define FSTG (4 * QK_TILE + 2 * V_TILE) // 71680
#define FOFF_S0 (4 * QK_TILE)           // 36864
#define FOFF_LAM (FOFF_S0 + 2 * FSTG)   // 180224
#define FL_SMEM (FOFF_LAM + 16)

__global__ __launch_bounds__(256, 1)
void flash_mma_kernel(const __nv_bfloat16* __restrict__ Qhi, const __nv_bfloat16* __restrict__ Qlo,
                      const __nv_bfloat16* __restrict__ Khi, const __nv_bfloat16* __restrict__ Klo,
                      const __nv_bfloat16* __restrict__ Vhi, const __nv_bfloat16* __restrict__ Vlo,
                      const float* __restrict__ lq1, const float* __restrict__ lk1,
                      const float* __restrict__ lq2, const float* __restrict__ lk2,
                      const float* __restrict__ lnw, const float* __restrict__ lnb,
                      __nv_bfloat16* __restrict__ Ahi, __nv_bfloat16* __restrict__ Alo)
{
    extern __shared__ __align__(16) uint8_t smraw[];
    const uint32_t sbase = smem_u32(smraw);
    float* sOut = (float*)smraw;
    float* sLam = (float*)(smraw + FOFF_LAM);

    const int tid = threadIdx.x;
    const int lane = tid & 31;
    const int wid = tid >> 5;
    const int br = wid >> 2;
    const int rbase = (wid & 3) * 16;
    const int g = lane >> 2;
    const int tg = lane & 3;

    const int qt = (int)gridDim.x - 1 - (int)blockIdx.x;
    const int h = blockIdx.y;
    const int b = blockIdx.z;
    const int q0t = qt * 64;
    const size_t rowBase = (size_t)b * S_LEN;
    const int colH = h * 128;

    // ---- inline lambda (warp 0) ----
    if (wid == 0) {
        float d1 = lq1[lane] * lk1[lane] + lq1[lane + 32] * lk1[lane + 32];
        float d2 = lq2[lane] * lk2[lane] + lq2[lane + 32] * lk2[lane + 32];
#pragma unroll
        for (int ofs = 16; ofs > 0; ofs >>= 1) {
            d1 += __shfl_xor_sync(0xffffffffu, d1, ofs);
            d2 += __shfl_xor_sync(0xffffffffu, d2, ofs);
        }
        if (lane == 0) sLam[0] = expf(d1) - expf(d2) + LAMBDA_INIT_F;
    }

    // ---- Q tiles ----
#pragma unroll
    for (int it = 0; it < 8; it++) {
        int idx = tid + 256 * it;
        int ch = idx & 7, r = (idx >> 3) & 63, t = idx >> 9;
        const __nv_bfloat16* src = ((t & 1) ? Qlo : Qhi)
            + (rowBase + q0t + r) * D_EMB + colH + (t >> 1) * 64 + ch * 8;
        cp16(sbase + FOFF_Q + t * QK_TILE + r * PQB + ch * 16, src);
    }
    asm volatile("cp.async.commit_group;");
    asm volatile("cp.async.wait_group 0;");
    __syncthreads();

    uint32_t qh[4][4], ql[4][4];
    {
        uint32_t qoff = (uint32_t)(rbase + (lane & 15)) * PQB + ((lane >> 4) << 4);
        uint32_t bh_ = sbase + FOFF_Q + (br * 2) * QK_TILE;
#pragma unroll
        for (int s = 0; s < 4; s++) {
            ldmx4(qh[s], bh_ + qoff + s * 32);
            ldmx4(ql[s], bh_ + QK_TILE + qoff + s * 32);
        }
    }

    auto load_kv = [&](int kt) {
        uint32_t stb = sbase + FOFF_S0 + (kt & 1) * FSTG;
#pragma unroll
        for (int it = 0; it < 8; it++) {
            int idx = tid + 256 * it;
            int ch = idx & 7, r = (idx >> 3) & 63, t = idx >> 9;
            const __nv_bfloat16* src = ((t & 1) ? Klo : Khi)
                + (rowBase + (size_t)kt * 64 + r) * D_EMB + colH + (t >> 1) * 64 + ch * 8;
            cp16(stb + t * QK_TILE + r * PQB + ch * 16, src);
        }
#pragma unroll
        for (int it = 0; it < 8; it++) {
            int idx = tid + 256 * it;
            int ch = idx & 15, r = (idx >> 4) & 63, t = idx >> 10;
            const __nv_bfloat16* src = (t ? Vlo : Vhi)
                + (rowBase + (size_t)kt * 64 + r) * D_EMB + colH + ch * 8;
            cp16(stb + 4 * QK_TILE + t * V_TILE + r * PVB + ch * 16, src);
        }
        asm volatile("cp.async.commit_group;");
    };

    float o[16][4];
#pragma unroll
    for (int i = 0; i < 16; i++)
#pragma unroll
        for (int j = 0; j < 4; j++) o[i][j] = 0.f;
    float m_a = -1e30f, m_b = -1e30f, l_a = 0.f, l_b = 0.f;

    load_kv(0);

    for (int kt = 0; kt <= qt; kt++) {
        if (kt < qt) {
            load_kv(kt + 1);
            asm volatile("cp.async.wait_group 1;");
        } else {
            asm volatile("cp.async.wait_group 0;");
        }
        __syncthreads();

        const uint32_t stb = sbase + FOFF_S0 + (kt & 1) * FSTG;

        float sc[8][4];
#pragma unroll
        for (int i = 0; i < 8; i++)
#pragma unroll
            for (int j = 0; j < 4; j++) sc[i][j] = 0.f;

        const uint32_t kbh = stb + (br * 2) * QK_TILE;
        const uint32_t koff = (uint32_t)(lane & 7) * PQB + ((lane >> 3) << 4);
#pragma unroll
        for (int nt = 0; nt < 8; nt++) {
            uint32_t a = koff + (uint32_t)nt * 8 * PQB;
            uint32_t kh0[4], kh1[4], kl0[4], kl1[4];
            ldmx4(kh0, kbh + a);
            ldmx4(kh1, kbh + a + 64);
            ldmx4(kl0, kbh + QK_TILE + a);
            ldmx4(kl1, kbh + QK_TILE + a + 64);
            mma_bf16(sc[nt], qh[0], &kh0[0]);
            mma_bf16(sc[nt], ql[0], &kh0[0]);
            mma_bf16(sc[nt], qh[0], &kl0[0]);
            mma_bf16(sc[nt], qh[1], &kh0[2]);
            mma_bf16(sc[nt], ql[1], &kh0[2]);
            mma_bf16(sc[nt], qh[1], &kl0[2]);
            mma_bf16(sc[nt], qh[2], &kh1[0]);
            mma_bf16(sc[nt], ql[2], &kh1[0]);
            mma_bf16(sc[nt], qh[2], &kl1[0]);
            mma_bf16(sc[nt], qh[3], &kh1[2]);
            mma_bf16(sc[nt], ql[3], &kh1[2]);
            mma_bf16(sc[nt], qh[3], &kl1[2]);
        }

        const bool diag = (kt == qt);
        float mxa = -1e30f, mxb = -1e30f;
#pragma unroll
        for (int nt = 0; nt < 8; nt++) {
            int c0 = nt * 8 + 2 * tg;
#pragma unroll
            for (int e = 0; e < 4; e++) {
                int row = rbase + g + ((e >> 1) << 3);
                int col = c0 + (e & 1);
                float v = sc[nt][e] * 0.125f;
                if (diag && col > row) v = -1e30f;
                sc[nt][e] = v;
            }
            mxa = fmaxf(mxa, fmaxf(sc[nt][0], sc[nt][1]));
            mxb = fmaxf(mxb, fmaxf(sc[nt][2], sc[nt][3]));
        }
        mxa = fmaxf(mxa, __shfl_xor_sync(0xffffffffu, mxa, 1));
        mxa = fmaxf(mxa, __shfl_xor_sync(0xffffffffu, mxa, 2));
        mxb = fmaxf(mxb, __shfl_xor_sync(0xffffffffu, mxb, 1));
        mxb = fmaxf(mxb, __shfl_xor_sync(0xffffffffu, mxb, 2));
        float mna = fmaxf(m_a, mxa), mnb = fmaxf(m_b, mxb);
        float alf_a = fexp(m_a - mna), alf_b = fexp(m_b - mnb);
        m_a = mna; m_b = mnb;

        float suma = 0.f, sumb = 0.f;
        uint32_t ph[4][4], pl[4][4];
#pragma unroll
        for (int s2 = 0; s2 < 4; s2++) {
#pragma unroll
            for (int hf = 0; hf < 2; hf++) {
                int nt = 2 * s2 + hf;
                float p0 = fexp(sc[nt][0] - m_a);
                float p1 = fexp(sc[nt][1] - m_a);
                float p2 = fexp(sc[nt][2] - m_b);
                float p3 = fexp(sc[nt][3] - m_b);
                suma += p0 + p1; sumb += p2 + p3;
                __nv_bfloat16 h0 = __float2bfloat16(p0);
                __nv_bfloat16 h1 = __float2bfloat16(p1);
                __nv_bfloat16 h2 = __float2bfloat16(p2);
                __nv_bfloat16 h3 = __float2bfloat16(p3);
                __nv_bfloat162 t01 = __halves2bfloat162(h0, h1);
                __nv_bfloat162 t23 = __halves2bfloat162(h2, h3);
                ph[s2][hf * 2 + 0] = *(uint32_t*)&t01;
                ph[s2][hf * 2 + 1] = *(uint32_t*)&t23;
                pl[s2][hf * 2 + 0] = pack_bf16(p0 - __bfloat162float(h0),
                                               p1 - __bfloat162float(h1));
                pl[s2][hf * 2 + 1] = pack_bf16(p2 - __bfloat162float(h2),
                                               p3 - __bfloat162float(h3));
            }
        }
        suma += __shfl_xor_sync(0xffffffffu, suma, 1);
        suma += __shfl_xor_sync(0xffffffffu, suma, 2);
        sumb += __shfl_xor_sync(0xffffffffu, sumb, 1);
        sumb += __shfl_xor_sync(0xffffffffu, sumb, 2);
        l_a = alf_a * l_a + suma;
        l_b = alf_b * l_b + sumb;

#pragma unroll
        for (int vt = 0; vt < 16; vt++) {
            o[vt][0] *= alf_a; o[vt][1] *= alf_a;
            o[vt][2] *= alf_b; o[vt][3] *= alf_b;
        }

        const uint32_t vb = stb + 4 * QK_TILE;
        const uint32_t vrow4 = (uint32_t)(lane & 15) * PVB + ((lane >> 4) << 4);
#pragma unroll
        for (int vt2 = 0; vt2 < 8; vt2++) {
#pragma unroll
            for (int s2 = 0; s2 < 4; s2++) {
                uint32_t addr = (uint32_t)(s2 * 16) * PVB + vrow4 + vt2 * 32;
                uint32_t bh4[4], bl4[4];
                ldmx4t(bh4, vb + addr);
                ldmx4t(bl4, vb + V_TILE + addr);
                mma_bf16(o[2 * vt2],     ph[s2], &bh4[0]);
                mma_bf16(o[2 * vt2],     pl[s2], &bh4[0]);
                mma_bf16(o[2 * vt2],     ph[s2], &bl4[0]);
                mma_bf16(o[2 * vt2 + 1], ph[s2], &bh4[2]);
                mma_bf16(o[2 * vt2 + 1], pl[s2], &bh4[2]);
                mma_bf16(o[2 * vt2 + 1], ph[s2], &bl4[2]);
            }
        }
        __syncthreads();
    }

    float lam = sLam[0];
    float ra = 1.0f / l_a, rb = 1.0f / l_b;

    if (br == 0) {
#pragma unroll
        for (int vt = 0; vt < 16; vt++) {
            int c = vt * 8 + 2 * tg;
            *(float2*)&sOut[(rbase + g) * 128 + c] = make_float2(o[vt][0] * ra, o[vt][1] * ra);
            *(float2*)&sOut[(rbase + g + 8) * 128 + c] = make_float2(o[vt][2] * rb, o[vt][3] * rb);
        }
    }
    __syncthreads();
    if (br == 1) {
#pragma unroll
        for (int vt = 0; vt < 16; vt++) {
            int c = vt * 8 + 2 * tg;
            float2* p0 = (float2*)&sOut[(rbase + g) * 128 + c];
            float2 v0 = *p0;
            v0.x -= lam * o[vt][0] * ra; v0.y -= lam * o[vt][1] * ra;
            *p0 = v0;
            float2* p1 = (float2*)&sOut[(rbase + g + 8) * 128 + c];
            float2 v1 = *p1;
            v1.x -= lam * o[vt][2] * rb; v1.y -= lam * o[vt][3] * rb;
            *p1 = v1;
        }
    }
    __syncthreads();

    // ---- RMSNorm + scale + split bf16 write ----
    {
        int r = tid >> 2;
        int q4 = tid & 3;
        float ss = 0.f;
#pragma unroll
        for (int u = 0; u < 32; u++) {
            float v = sOut[r * 128 + q4 * 32 + u];
            ss += v * v;
        }
        ss += __shfl_xor_sync(0xffffffffu, ss, 1);
        ss += __shfl_xor_sync(0xffffffffu, ss, 2);
        float rn = rsqrtf(ss * (1.0f / 128.0f) + 1e-8f);
        size_t outrow = (rowBase + q0t + r) * D_EMB + colH;
#pragma unroll
        for (int u = 0; u < 32; u += 2) {
            int e = q4 * 32 + u;
            float v0 = (sOut[r * 128 + e] * rn * lnw[e] + lnb[e]) * ONE_MINUS_LI_F;
            float v1 = (sOut[r * 128 + e + 1] * rn * lnw[e + 1] + lnb[e + 1]) * ONE_MINUS_LI_F;
            uint32_t hw, lw;
            split2(v0, v1, hw, lw);
            *(uint32_t*)&Ahi[outrow + e] = hw;
            *(uint32_t*)&Alo[outrow + e] = lw;
        }
    }
}

// ---------------- launch ---------------------------------------------------
extern "C" void kernel_launch(void* const* d_in, const int* in_sizes, int n_in,
                              void* d_out, int out_size)
{
    (void)in_sizes; (void)n_in; (void)out_size;
    const float* x   = (const float*)d_in[0];
    const float* Wq  = (const float*)d_in[1];
    const float* Wk  = (const float*)d_in[2];
    const float* Wv  = (const float*)d_in[3];
    const float* Wo  = (const float*)d_in[4];
    const float* lq1 = (const float*)d_in[5];
    const float* lk1 = (const float*)d_in[6];
    const float* lq2 = (const float*)d_in[7];
    const float* lk2 = (const float*)d_in[8];
    const float* lnw = (const float*)d_in[9];
    const float* lnb = (const float*)d_in[10];
    float* out = (float*)d_out;

    __nv_bfloat16 *xhi, *xlo, *whi, *wlo, *ahi, *alo;
    __nv_bfloat16 *qhi, *qlo, *khi, *klo, *vhi, *vlo;
    cudaGetSymbolAddress((void**)&xhi, g_xhi);
    cudaGetSymbolAddress((void**)&xlo, g_xlo);
    cudaGetSymbolAddress((void**)&whi, g_whi);
    cudaGetSymbolAddress((void**)&wlo, g_wlo);
    cudaGetSymbolAddress((void**)&ahi, g_ahi);
    cudaGetSymbolAddress((void**)&alo, g_alo);
    cudaGetSymbolAddress((void**)&qhi, g_Qhi);
    cudaGetSymbolAddress((void**)&qlo, g_Qlo);
    cudaGetSymbolAddress((void**)&khi, g_Khi);
    cudaGetSymbolAddress((void**)&klo, g_Klo);
    cudaGetSymbolAddress((void**)&vhi, g_Vhi);
    cudaGetSymbolAddress((void**)&vlo, g_Vlo);

    const int nx4 = (MROWS * D_EMB) / 4;
    const int nw4 = (D_EMB * D_EMB) / 4;

    dim3 wsg((nw4 + 255) / 256, 4);
    wsplit_all_kernel<<<wsg, 256>>>(Wq, Wk, Wv, Wo, whi, wlo);
    split_kernel<<<(nx4 + 255) / 256, 256>>>(x, xhi, xlo, nx4);

    cudaFuncSetAttribute(gemm_bf16x3<0>, cudaFuncAttributeMaxDynamicSharedMemorySize, G_SMEM);
    cudaFuncSetAttribute(gemm_bf16x3<1>, cudaFuncAttributeMaxDynamicSharedMemorySize, G_SMEM);

    // fused QKV projection + rope + split epilogue
    dim3 gqkv(NQKV / 128, MROWS / 128);   // (48, 32)
    gemm_bf16x3<1><<<gqkv, 256, G_SMEM>>>(xhi, xlo, whi, wlo, nullptr,
                                          MROWS, NQKV, D_EMB, WCOLS, 0);

    cudaFuncSetAttribute(flash_mma_kernel, cudaFuncAttributeMaxDynamicSharedMemorySize, FL_SMEM);
    flash_mma_kernel<<<dim3(32, NHEAD, BATCH), 256, FL_SMEM>>>(
        qhi, qlo, khi, klo, vhi, vlo, lq1, lk1, lq2, lk2, lnw, lnb, ahi, alo);

    // output projection
    dim3 go(D_EMB / 128, MROWS / 128);    // (16, 32)
    gemm_bf16x3<0><<<go, 256, G_SMEM>>>(ahi, alo, whi + 6144, wlo + 6144, out,
                                        MROWS, D_EMB, D_EMB, WCOLS, D_EMB);
}

// round 10
// speedup vs baseline: 1.2758x; 1.0183x over previous
#include <cuda_runtime.h>
#include <cuda_bf16.h>
#include <cstdint>
#include <cstddef>

#define S_LEN 2048
#define D_EMB 2048
#define NHEAD 16
#define HDIM 64
#define DVDIM 128
#define BATCH 2
#define MROWS (BATCH * S_LEN)   // 4096
#define NQKV 6144
#define WCOLS 8192

#define LAMBDA_INIT_F 0.78360576653162435f
#define ONE_MINUS_LI_F 0.21639423346837565f
#define LN1E4_OVER_32 (9.210340371976184f / 32.0f)
#define SCALE_LOG2 0.18033688011112042f   // 0.125 * log2(e)

// ---------------- scratch (device globals) -------------------------------
__device__ float2 g_rope[S_LEN * 32];          // [s][j] -> (cos, sin)

__device__ __nv_bfloat16 g_xhi[(size_t)MROWS * D_EMB];
__device__ __nv_bfloat16 g_xlo[(size_t)MROWS * D_EMB];
__device__ __nv_bfloat16 g_whi[(size_t)D_EMB * WCOLS];   // [K, Wq|Wk|Wv|Wo]
__device__ __nv_bfloat16 g_wlo[(size_t)D_EMB * WCOLS];
__device__ __nv_bfloat16 g_ahi[(size_t)MROWS * D_EMB];
__device__ __nv_bfloat16 g_alo[(size_t)MROWS * D_EMB];

__device__ __nv_bfloat16 g_Qhi[(size_t)MROWS * D_EMB];
__device__ __nv_bfloat16 g_Qlo[(size_t)MROWS * D_EMB];
__device__ __nv_bfloat16 g_Khi[(size_t)MROWS * D_EMB];
__device__ __nv_bfloat16 g_Klo[(size_t)MROWS * D_EMB];
__device__ __nv_bfloat16 g_Vhi[(size_t)MROWS * D_EMB];
__device__ __nv_bfloat16 g_Vlo[(size_t)MROWS * D_EMB];

// ---------------- common PTX helpers --------------------------------------
__device__ __forceinline__ uint32_t smem_u32(const void* p) {
    return (uint32_t)__cvta_generic_to_shared(p);
}
__device__ __forceinline__ void cp16(uint32_t s, const void* g) {
    asm volatile("cp.async.ca.shared.global [%0], [%1], 16;" :: "r"(s), "l"(g));
}
__device__ __forceinline__ void cp16cg(uint32_t s, const void* g) {
    asm volatile("cp.async.cg.shared.global [%0], [%1], 16;" :: "r"(s), "l"(g));
}
__device__ __forceinline__ void ldmx4(uint32_t r[4], uint32_t addr) {
    asm volatile("ldmatrix.sync.aligned.m8n8.x4.shared.b16 {%0,%1,%2,%3}, [%4];"
        : "=r"(r[0]), "=r"(r[1]), "=r"(r[2]), "=r"(r[3]) : "r"(addr));
}
__device__ __forceinline__ void ldmx4t(uint32_t r[4], uint32_t addr) {
    asm volatile("ldmatrix.sync.aligned.m8n8.x4.trans.shared.b16 {%0,%1,%2,%3}, [%4];"
        : "=r"(r[0]), "=r"(r[1]), "=r"(r[2]), "=r"(r[3]) : "r"(addr));
}
__device__ __forceinline__ void mma_bf16(float c[4], const uint32_t a[4], const uint32_t b[2]) {
    asm volatile("mma.sync.aligned.m16n8k16.row.col.f32.bf16.bf16.f32 "
        "{%0,%1,%2,%3}, {%4,%5,%6,%7}, {%8,%9}, {%0,%1,%2,%3};"
        : "+f"(c[0]), "+f"(c[1]), "+f"(c[2]), "+f"(c[3])
        : "r"(a[0]), "r"(a[1]), "r"(a[2]), "r"(a[3]), "r"(b[0]), "r"(b[1]));
}
__device__ __forceinline__ uint32_t pack_bf16(float lo, float hi) {
    uint32_t r;
    asm("cvt.rn.bf16x2.f32 %0, %1, %2;" : "=r"(r) : "f"(hi), "f"(lo));
    return r;
}
// exp2 on the (idle) MUFU pipe; saturates to 0 for very negative x
__device__ __forceinline__ float fexp2(float x) {
    float r;
    asm("ex2.approx.f32 %0, %1;" : "=f"(r) : "f"(x));
    return r;
}
__device__ __forceinline__ void split2(float v0, float v1, uint32_t& hw, uint32_t& lw) {
    __nv_bfloat16 h0 = __float2bfloat16(v0);
    __nv_bfloat16 h1 = __float2bfloat16(v1);
    __nv_bfloat162 hh = __halves2bfloat162(h0, h1);
    hw = *(uint32_t*)&hh;
    lw = pack_bf16(v0 - __bfloat162float(h0), v1 - __bfloat162float(h1));
}

// =================== fp32 -> (bf16 hi, bf16 lo) split ====================
__global__ void split_kernel(const float* __restrict__ in,
                             __nv_bfloat16* __restrict__ hi,
                             __nv_bfloat16* __restrict__ lo, int n4)
{
    int i = blockIdx.x * blockDim.x + threadIdx.x;
    if (i >= n4) return;
    float4 v = ((const float4*)in)[i];
    uint32_t h0, l0, h1, l1;
    split2(v.x, v.y, h0, l0);
    split2(v.z, v.w, h1, l1);
    ((uint32_t*)hi)[2 * i]     = h0;
    ((uint32_t*)hi)[2 * i + 1] = h1;
    ((uint32_t*)lo)[2 * i]     = l0;
    ((uint32_t*)lo)[2 * i + 1] = l1;
}

// ===== all 4 W -> packed [2048, 8192] + split; also fills rope table =====
__global__ void wsplit_all_kernel(const float* __restrict__ W0, const float* __restrict__ W1,
                                  const float* __restrict__ W2, const float* __restrict__ W3,
                                  __nv_bfloat16* __restrict__ hi, __nv_bfloat16* __restrict__ lo)
{
    const int wsel = blockIdx.y;
    if (wsel == 0 && blockIdx.x < 256) {
        int idx = blockIdx.x * 256 + threadIdx.x;
        int s = idx >> 5, j = idx & 31;
        float inv = expf(-(float)j * LN1E4_OVER_32);
        float sn, cs;
        sincosf((float)s * inv, &sn, &cs);
        g_rope[idx] = make_float2(cs, sn);
    }
    int i = blockIdx.x * blockDim.x + threadIdx.x;
    if (i >= (D_EMB * D_EMB) / 4) return;
    const float* in = (wsel == 0) ? W0 : (wsel == 1) ? W1 : (wsel == 2) ? W2 : W3;
    int r = i >> 9;
    int c4 = (i & 511) << 2;
    float4 v = ((const float4*)in)[i];
    uint32_t h0, l0, h1, l1;
    split2(v.x, v.y, h0, l0);
    split2(v.z, v.w, h1, l1);
    size_t o = ((size_t)r * WCOLS + wsel * 2048 + c4) >> 1;
    ((uint32_t*)hi)[o]     = h0;
    ((uint32_t*)hi)[o + 1] = h1;
    ((uint32_t*)lo)[o]     = l0;
    ((uint32_t*)lo)[o + 1] = l1;
}

// =================== tensor-core GEMM (bf16 x3 split) ====================
// C[M,N] = A[M,K] * B[K,N]. 256 threads, 128x128 tile, BK=32, 3 stages,
// prefetch distance 2, 1 barrier/iter, 2 CTAs per SM.
#define GBK 32
#define GAP 80
#define GBP 272
#define GOFF_AL (128 * GAP)
#define GOFF_BH (2 * 128 * GAP)
#define GOFF_BL (GOFF_BH + GBK * GBP)
#define GSTAGE (GOFF_BL + GBK * GBP)
#define G_SMEM (3 * GSTAGE)

template <int MODE>
__global__ __launch_bounds__(256, 2)
void gemm_bf16x3(const __nv_bfloat16* __restrict__ Ahi, const __nv_bfloat16* __restrict__ Alo,
                 const __nv_bfloat16* __restrict__ Bhi, const __nv_bfloat16* __restrict__ Blo,
                 float* __restrict__ C, int M, int N, int K, int ldb, int ldc)
{
    extern __shared__ __align__(16) uint8_t gsm[];
    const uint32_t sbase = smem_u32(gsm);
    const int tid = threadIdx.x;
    const int lane = tid & 31;
    const int wid = tid >> 5;
    const int m0 = blockIdx.y * 128;
    const int n0 = blockIdx.x * 128;

    const int wm = wid & 3;
    const int wn = wid >> 2;

    const int KT = K / GBK;

    auto load_stage = [&](int t) {
        uint32_t st = sbase + (t % 3) * GSTAGE;
        int k0 = t * GBK;
#pragma unroll
        for (int j = 0; j < 8; j++) {
            int cid = tid + 256 * j;
            if (cid < 1024) {
                int hl = cid >> 9;
                int sub = cid & 511;
                int row = sub >> 2;
                int ch = sub & 3;
                const __nv_bfloat16* src = (hl ? Alo : Ahi)
                    + (size_t)(m0 + row) * K + k0 + ch * 8;
                cp16cg(st + (hl ? GOFF_AL : 0) + row * GAP + ch * 16, src);
            } else {
                int c2 = cid - 1024;
                int hl = c2 >> 9;
                int sub = c2 & 511;
                int row = sub >> 4;
                int ch = sub & 15;
                const __nv_bfloat16* src = (hl ? Blo : Bhi)
                    + (size_t)(k0 + row) * ldb + n0 + ch * 8;
                cp16cg(st + (hl ? GOFF_BL : GOFF_BH) + row * GBP + ch * 16, src);
            }
        }
        asm volatile("cp.async.commit_group;");
    };

    load_stage(0);
    load_stage(1);

    float acc[2][8][4];
#pragma unroll
    for (int i = 0; i < 2; i++)
#pragma unroll
        for (int j = 0; j < 8; j++)
#pragma unroll
            for (int l = 0; l < 4; l++) acc[i][j][l] = 0.f;

    const uint32_t aoff = (uint32_t)(wm * 32 + (lane & 15)) * GAP + ((lane >> 4) & 1) * 16;
    const uint32_t boff = (uint32_t)(lane & 15) * GBP + (uint32_t)wn * 128
                        + ((lane >> 4) & 1) * 16;

    for (int t = 0; t < KT; t++) {
        if (t + 1 < KT) asm volatile("cp.async.wait_group 1;");
        else            asm volatile("cp.async.wait_group 0;");
        __syncthreads();
        if (t + 2 < KT) load_stage(t + 2);

        uint32_t st = sbase + (t % 3) * GSTAGE;
#pragma unroll
        for (int kk = 0; kk < 2; kk++) {
            uint32_t ah[2][4], al[2][4];
            ldmx4(ah[0], st + aoff + kk * 32);
            ldmx4(ah[1], st + aoff + 16 * GAP + kk * 32);
            ldmx4(al[0], st + GOFF_AL + aoff + kk * 32);
            ldmx4(al[1], st + GOFF_AL + aoff + 16 * GAP + kk * 32);
            uint32_t bb = st + boff + (uint32_t)kk * 16 * GBP;
#pragma unroll
            for (int half = 0; half < 2; half++) {
                uint32_t bh[8], bl[8];
                ldmx4t(&bh[0], bb + GOFF_BH + half * 64);
                ldmx4t(&bh[4], bb + GOFF_BH + half * 64 + 32);
                ldmx4t(&bl[0], bb + GOFF_BL + half * 64);
                ldmx4t(&bl[4], bb + GOFF_BL + half * 64 + 32);
#pragma unroll
                for (int mt = 0; mt < 2; mt++)
#pragma unroll
                    for (int nt = 0; nt < 4; nt++) {
                        int ng = half * 4 + nt;
                        mma_bf16(acc[mt][ng], ah[mt], &bh[nt * 2]);
                        mma_bf16(acc[mt][ng], al[mt], &bh[nt * 2]);
                        mma_bf16(acc[mt][ng], ah[mt], &bl[nt * 2]);
                    }
            }
        }
    }

    // epilogue
    const int gid = lane >> 2, tig = lane & 3;
    if (MODE == 0) {
#pragma unroll
        for (int mt = 0; mt < 2; mt++) {
            int row = m0 + wm * 32 + mt * 16 + gid;
#pragma unroll
            for (int nt = 0; nt < 8; nt++) {
                int col = n0 + wn * 64 + nt * 8 + 2 * tig;
                *(float2*)&C[(size_t)row * ldc + col] = make_float2(acc[mt][nt][0], acc[mt][nt][1]);
                *(float2*)&C[(size_t)(row + 8) * ldc + col] = make_float2(acc[mt][nt][2], acc[mt][nt][3]);
            }
        }
    } else {
        const int region = n0 >> 11;    // 0=Q, 1=K, 2=V
        __nv_bfloat16* dh = (region == 0) ? g_Qhi : (region == 1) ? g_Khi : g_Vhi;
        __nv_bfloat16* dl = (region == 0) ? g_Qlo : (region == 1) ? g_Klo : g_Vlo;
#pragma unroll
        for (int mt = 0; mt < 2; mt++) {
#pragma unroll
            for (int nt = 0; nt < 8; nt++) {
                int col = n0 + wn * 64 + nt * 8 + 2 * tig;
                int cl = col & 2047;
                int j = (cl & 63) >> 1;
#pragma unroll
                for (int rr = 0; rr < 2; rr++) {
                    int row = m0 + wm * 32 + mt * 16 + gid + rr * 8;
                    float v0 = acc[mt][nt][rr * 2 + 0];
                    float v1 = acc[mt][nt][rr * 2 + 1];
                    if (region < 2) {
                        int s = row & (S_LEN - 1);
                        float2 t = g_rope[(s << 5) + j];
                        float f0 = v0 * t.x - v1 * t.y;
                        float f1 = v1 * t.x + v0 * t.y;
                        v0 = f0; v1 = f1;
                    }
                    uint32_t hw, lw;
                    split2(v0, v1, hw, lw);
                    size_t o = ((size_t)row * D_EMB + cl) >> 1;
                    ((uint32_t*)dh)[o] = hw;
                    ((uint32_t*)dl)[o] = lw;
                }
            }
        }
    }
}

// ================= MMA dual-branch flash attention (double-buffered) ======
#define PQB 144
#define PVB 272
#define QK_TILE (64 * PQB)              // 9216
#define V_TILE  (64 * PVB)              // 17408
#define FOFF_Q 0
#define FSTG (4 * QK_TILE + 2 * V_TILE) // 71680
#define FOFF_S0 (4 * QK_TILE)           // 36864
#define FOFF_LAM (FOFF_S0 + 2 * FSTG)   // 180224
#define FL_SMEM (FOFF_LAM + 16)

__global__ __launch_bounds__(256, 1)
void flash_mma_kernel(const __nv_bfloat16* __restrict__ Qhi, const __nv_bfloat16* __restrict__ Qlo,
                      const __nv_bfloat16* __restrict__ Khi, const __nv_bfloat16* __restrict__ Klo,
                      const __nv_bfloat16* __restrict__ Vhi, const __nv_bfloat16* __restrict__ Vlo,
                      const float* __restrict__ lq1, const float* __restrict__ lk1,
                      const float* __restrict__ lq2, const float* __restrict__ lk2,
                      const float* __restrict__ lnw, const float* __restrict__ lnb,
                      __nv_bfloat16* __restrict__ Ahi, __nv_bfloat16* __restrict__ Alo)
{
    extern __shared__ __align__(16) uint8_t smraw[];
    const uint32_t sbase = smem_u32(smraw);
    float* sOut = (float*)smraw;
    float* sLam = (float*)(smraw + FOFF_LAM);

    const int tid = threadIdx.x;
    const int lane = tid & 31;
    const int wid = tid >> 5;
    const int br = wid >> 2;
    const int rbase = (wid & 3) * 16;
    const int g = lane >> 2;
    const int tg = lane & 3;

    const int qt = (int)gridDim.x - 1 - (int)blockIdx.x;
    const int h = blockIdx.y;
    const int b = blockIdx.z;
    const int q0t = qt * 64;
    const size_t rowBase = (size_t)b * S_LEN;
    const int colH = h * 128;

    // ---- inline lambda (warp 0) ----
    if (wid == 0) {
        float d1 = lq1[lane] * lk1[lane] + lq1[lane + 32] * lk1[lane + 32];
        float d2 = lq2[lane] * lk2[lane] + lq2[lane + 32] * lk2[lane + 32];
#pragma unroll
        for (int ofs = 16; ofs > 0; ofs >>= 1) {
            d1 += __shfl_xor_sync(0xffffffffu, d1, ofs);
            d2 += __shfl_xor_sync(0xffffffffu, d2, ofs);
        }
        if (lane == 0) sLam[0] = expf(d1) - expf(d2) + LAMBDA_INIT_F;
    }

    // ---- Q tiles ----
#pragma unroll
    for (int it = 0; it < 8; it++) {
        int idx = tid + 256 * it;
        int ch = idx & 7, r = (idx >> 3) & 63, t = idx >> 9;
        const __nv_bfloat16* src = ((t & 1) ? Qlo : Qhi)
            + (rowBase + q0t + r) * D_EMB + colH + (t >> 1) * 64 + ch * 8;
        cp16(sbase + FOFF_Q + t * QK_TILE + r * PQB + ch * 16, src);
    }
    asm volatile("cp.async.commit_group;");
    asm volatile("cp.async.wait_group 0;");
    __syncthreads();

    uint32_t qh[4][4], ql[4][4];
    {
        uint32_t qoff = (uint32_t)(rbase + (lane & 15)) * PQB + ((lane >> 4) << 4);
        uint32_t bh_ = sbase + FOFF_Q + (br * 2) * QK_TILE;
#pragma unroll
        for (int s = 0; s < 4; s++) {
            ldmx4(qh[s], bh_ + qoff + s * 32);
            ldmx4(ql[s], bh_ + QK_TILE + qoff + s * 32);
        }
    }

    auto load_kv = [&](int kt) {
        uint32_t stb = sbase + FOFF_S0 + (kt & 1) * FSTG;
#pragma unroll
        for (int it = 0; it < 8; it++) {
            int idx = tid + 256 * it;
            int ch = idx & 7, r = (idx >> 3) & 63, t = idx >> 9;
            const __nv_bfloat16* src = ((t & 1) ? Klo : Khi)
                + (rowBase + (size_t)kt * 64 + r) * D_EMB + colH + (t >> 1) * 64 + ch * 8;
            cp16(stb + t * QK_TILE + r * PQB + ch * 16, src);
        }
#pragma unroll
        for (int it = 0; it < 8; it++) {
            int idx = tid + 256 * it;
            int ch = idx & 15, r = (idx >> 4) & 63, t = idx >> 10;
            const __nv_bfloat16* src = (t ? Vlo : Vhi)
                + (rowBase + (size_t)kt * 64 + r) * D_EMB + colH + ch * 8;
            cp16(stb + 4 * QK_TILE + t * V_TILE + r * PVB + ch * 16, src);
        }
        asm volatile("cp.async.commit_group;");
    };

    float o[16][4];
#pragma unroll
    for (int i = 0; i < 16; i++)
#pragma unroll
        for (int j = 0; j < 4; j++) o[i][j] = 0.f;
    float m_a = -1e30f, m_b = -1e30f, l_a = 0.f, l_b = 0.f;

    load_kv(0);

    for (int kt = 0; kt <= qt; kt++) {
        if (kt < qt) {
            load_kv(kt + 1);
            asm volatile("cp.async.wait_group 1;");
        } else {
            asm volatile("cp.async.wait_group 0;");
        }
        __syncthreads();

        const uint32_t stb = sbase + FOFF_S0 + (kt & 1) * FSTG;

        float sc[8][4];
#pragma unroll
        for (int i = 0; i < 8; i++)
#pragma unroll
            for (int j = 0; j < 4; j++) sc[i][j] = 0.f;

        const uint32_t kbh = stb + (br * 2) * QK_TILE;
        const uint32_t koff = (uint32_t)(lane & 7) * PQB + ((lane >> 3) << 4);
#pragma unroll
        for (int nt = 0; nt < 8; nt++) {
            uint32_t a = koff + (uint32_t)nt * 8 * PQB;
            uint32_t kh0[4], kh1[4], kl0[4], kl1[4];
            ldmx4(kh0, kbh + a);
            ldmx4(kh1, kbh + a + 64);
            ldmx4(kl0, kbh + QK_TILE + a);
            ldmx4(kl1, kbh + QK_TILE + a + 64);
            mma_bf16(sc[nt], qh[0], &kh0[0]);
            mma_bf16(sc[nt], ql[0], &kh0[0]);
            mma_bf16(sc[nt], qh[0], &kl0[0]);
            mma_bf16(sc[nt], qh[1], &kh0[2]);
            mma_bf16(sc[nt], ql[1], &kh0[2]);
            mma_bf16(sc[nt], qh[1], &kl0[2]);
            mma_bf16(sc[nt], qh[2], &kh1[0]);
            mma_bf16(sc[nt], ql[2], &kh1[0]);
            mma_bf16(sc[nt], qh[2], &kl1[0]);
            mma_bf16(sc[nt], qh[3], &kh1[2]);
            mma_bf16(sc[nt], ql[3], &kh1[2]);
            mma_bf16(sc[nt], qh[3], &kl1[2]);
        }

        // ---- scale into log2 domain, mask, row max ----
        const bool diag = (kt == qt);
        float mxa = -1e30f, mxb = -1e30f;
#pragma unroll
        for (int nt = 0; nt < 8; nt++) {
            int c0 = nt * 8 + 2 * tg;
#pragma unroll
            for (int e = 0; e < 4; e++) {
                int row = rbase + g + ((e >> 1) << 3);
                int col = c0 + (e & 1);
                float v = sc[nt][e] * SCALE_LOG2;
                if (diag && col > row) v = -1e30f;
                sc[nt][e] = v;
            }
            mxa = fmaxf(mxa, fmaxf(sc[nt][0], sc[nt][1]));
            mxb = fmaxf(mxb, fmaxf(sc[nt][2], sc[nt][3]));
        }
        mxa = fmaxf(mxa, __shfl_xor_sync(0xffffffffu, mxa, 1));
        mxa = fmaxf(mxa, __shfl_xor_sync(0xffffffffu, mxa, 2));
        mxb = fmaxf(mxb, __shfl_xor_sync(0xffffffffu, mxb, 1));
        mxb = fmaxf(mxb, __shfl_xor_sync(0xffffffffu, mxb, 2));
        float mna = fmaxf(m_a, mxa), mnb = fmaxf(m_b, mxb);
        float alf_a = fexp2(m_a - mna), alf_b = fexp2(m_b - mnb);
        m_a = mna; m_b = mnb;

        float suma = 0.f, sumb = 0.f;
        uint32_t ph[4][4], pl[4][4];
#pragma unroll
        for (int s2 = 0; s2 < 4; s2++) {
#pragma unroll
            for (int hf = 0; hf < 2; hf++) {
                int nt = 2 * s2 + hf;
                float p0 = fexp2(sc[nt][0] - m_a);
                float p1 = fexp2(sc[nt][1] - m_a);
                float p2 = fexp2(sc[nt][2] - m_b);
                float p3 = fexp2(sc[nt][3] - m_b);
                suma += p0 + p1; sumb += p2 + p3;
                __nv_bfloat16 h0 = __float2bfloat16(p0);
                __nv_bfloat16 h1 = __float2bfloat16(p1);
                __nv_bfloat16 h2 = __float2bfloat16(p2);
                __nv_bfloat16 h3 = __float2bfloat16(p3);
                __nv_bfloat162 t01 = __halves2bfloat162(h0, h1);
                __nv_bfloat162 t23 = __halves2bfloat162(h2, h3);
                ph[s2][hf * 2 + 0] = *(uint32_t*)&t01;
                ph[s2][hf * 2 + 1] = *(uint32_t*)&t23;
                pl[s2][hf * 2 + 0] = pack_bf16(p0 - __bfloat162float(h0),
                                               p1 - __bfloat162float(h1));
                pl[s2][hf * 2 + 1] = pack_bf16(p2 - __bfloat162float(h2),
                                               p3 - __bfloat162float(h3));
            }
        }
        suma += __shfl_xor_sync(0xffffffffu, suma, 1);
        suma += __shfl_xor_sync(0xffffffffu, suma, 2);
        sumb += __shfl_xor_sync(0xffffffffu, sumb, 1);
        sumb += __shfl_xor_sync(0xffffffffu, sumb, 2);
        l_a = alf_a * l_a + suma;
        l_b = alf_b * l_b + sumb;

#pragma unroll
        for (int vt = 0; vt < 16; vt++) {
            o[vt][0] *= alf_a; o[vt][1] *= alf_a;
            o[vt][2] *= alf_b; o[vt][3] *= alf_b;
        }

        const uint32_t vb = stb + 4 * QK_TILE;
        const uint32_t vrow4 = (uint32_t)(lane & 15) * PVB + ((lane >> 4) << 4);
#pragma unroll
        for (int vt2 = 0; vt2 < 8; vt2++) {
#pragma unroll
            for (int s2 = 0; s2 < 4; s2++) {
                uint32_t addr = (uint32_t)(s2 * 16) * PVB + vrow4 + vt2 * 32;
                uint32_t bh4[4], bl4[4];
                ldmx4t(bh4, vb + addr);
                ldmx4t(bl4, vb + V_TILE + addr);
                mma_bf16(o[2 * vt2],     ph[s2], &bh4[0]);
                mma_bf16(o[2 * vt2],     pl[s2], &bh4[0]);
                mma_bf16(o[2 * vt2],     ph[s2], &bl4[0]);
                mma_bf16(o[2 * vt2 + 1], ph[s2], &bh4[2]);
                mma_bf16(o[2 * vt2 + 1], pl[s2], &bh4[2]);
                mma_bf16(o[2 * vt2 + 1], ph[s2], &bl4[2]);
            }
        }
        __syncthreads();
    }

    float lam = sLam[0];
    float ra = 1.0f / l_a, rb = 1.0f / l_b;

    if (br == 0) {
#pragma unroll
        for (int vt = 0; vt < 16; vt++) {
            int c = vt * 8 + 2 * tg;
            *(float2*)&sOut[(rbase + g) * 128 + c] = make_float2(o[vt][0] * ra, o[vt][1] * ra);
            *(float2*)&sOut[(rbase + g + 8) * 128 + c] = make_float2(o[vt][2] * rb, o[vt][3] * rb);
        }
    }
    __syncthreads();
    if (br == 1) {
#pragma unroll
        for (int vt = 0; vt < 16; vt++) {
            int c = vt * 8 + 2 * tg;
            float2* p0 = (float2*)&sOut[(rbase + g) * 128 + c];
            float2 v0 = *p0;
            v0.x -= lam * o[vt][0] * ra; v0.y -= lam * o[vt][1] * ra;
            *p0 = v0;
            float2* p1 = (float2*)&sOut[(rbase + g + 8) * 128 + c];
            float2 v1 = *p1;
            v1.x -= lam * o[vt][2] * rb; v1.y -= lam * o[vt][3] * rb;
            *p1 = v1;
        }
    }
    __syncthreads();

    // ---- RMSNorm + scale + split bf16 write ----
    {
        int r = tid >> 2;
        int q4 = tid & 3;
        float ss = 0.f;
#pragma unroll
        for (int u = 0; u < 32; u++) {
            float v = sOut[r * 128 + q4 * 32 + u];
            ss += v * v;
        }
        ss += __shfl_xor_sync(0xffffffffu, ss, 1);
        ss += __shfl_xor_sync(0xffffffffu, ss, 2);
        float rn = rsqrtf(ss * (1.0f / 128.0f) + 1e-8f);
        size_t outrow = (rowBase + q0t + r) * D_EMB + colH;
#pragma unroll
        for (int u = 0; u < 32; u += 2) {
            int e = q4 * 32 + u;
            float v0 = (sOut[r * 128 + e] * rn * lnw[e] + lnb[e]) * ONE_MINUS_LI_F;
            float v1 = (sOut[r * 128 + e + 1] * rn * lnw[e + 1] + lnb[e + 1]) * ONE_MINUS_LI_F;
            uint32_t hw, lw;
            split2(v0, v1, hw, lw);
            *(uint32_t*)&Ahi[outrow + e] = hw;
            *(uint32_t*)&Alo[outrow + e] = lw;
        }
    }
}

// ---------------- launch ---------------------------------------------------
extern "C" void kernel_launch(void* const* d_in, const int* in_sizes, int n_in,
                              void* d_out, int out_size)
{
    (void)in_sizes; (void)n_in; (void)out_size;
    const float* x   = (const float*)d_in[0];
    const float* Wq  = (const float*)d_in[1];
    const float* Wk  = (const float*)d_in[2];
    const float* Wv  = (const float*)d_in[3];
    const float* Wo  = (const float*)d_in[4];
    const float* lq1 = (const float*)d_in[5];
    const float* lk1 = (const float*)d_in[6];
    const float* lq2 = (const float*)d_in[7];
    const float* lk2 = (const float*)d_in[8];
    const float* lnw = (const float*)d_in[9];
    const float* lnb = (const float*)d_in[10];
    float* out = (float*)d_out;

    __nv_bfloat16 *xhi, *xlo, *whi, *wlo, *ahi, *alo;
    __nv_bfloat16 *qhi, *qlo, *khi, *klo, *vhi, *vlo;
    cudaGetSymbolAddress((void**)&xhi, g_xhi);
    cudaGetSymbolAddress((void**)&xlo, g_xlo);
    cudaGetSymbolAddress((void**)&whi, g_whi);
    cudaGetSymbolAddress((void**)&wlo, g_wlo);
    cudaGetSymbolAddress((void**)&ahi, g_ahi);
    cudaGetSymbolAddress((void**)&alo, g_alo);
    cudaGetSymbolAddress((void**)&qhi, g_Qhi);
    cudaGetSymbolAddress((void**)&qlo, g_Qlo);
    cudaGetSymbolAddress((void**)&khi, g_Khi);
    cudaGetSymbolAddress((void**)&klo, g_Klo);
    cudaGetSymbolAddress((void**)&vhi, g_Vhi);
    cudaGetSymbolAddress((void**)&vlo, g_Vlo);

    const int nx4 = (MROWS * D_EMB) / 4;
    const int nw4 = (D_EMB * D_EMB) / 4;

    dim3 wsg((nw4 + 255) / 256, 4);
    wsplit_all_kernel<<<wsg, 256>>>(Wq, Wk, Wv, Wo, whi, wlo);
    split_kernel<<<(nx4 + 255) / 256, 256>>>(x, xhi, xlo, nx4);

    cudaFuncSetAttribute(gemm_bf16x3<0>, cudaFuncAttributeMaxDynamicSharedMemorySize, G_SMEM);
    cudaFuncSetAttribute(gemm_bf16x3<1>, cudaFuncAttributeMaxDynamicSharedMemorySize, G_SMEM);

    // fused QKV projection + rope + split epilogue
    dim3 gqkv(NQKV / 128, MROWS / 128);   // (48, 32)
    gemm_bf16x3<1><<<gqkv, 256, G_SMEM>>>(xhi, xlo, whi, wlo, nullptr,
                                          MROWS, NQKV, D_EMB, WCOLS, 0);

    cudaFuncSetAttribute(flash_mma_kernel, cudaFuncAttributeMaxDynamicSharedMemorySize, FL_SMEM);
    flash_mma_kernel<<<dim3(32, NHEAD, BATCH), 256, FL_SMEM>>>(
        qhi, qlo, khi, klo, vhi, vlo, lq1, lk1, lq2, lk2, lnw, lnb, ahi, alo);

    // output projection
    dim3 go(D_EMB / 128, MROWS / 128);    // (16, 32)
    gemm_bf16x3<0><<<go, 256, G_SMEM>>>(ahi, alo, whi + 6144, wlo + 6144, out,
                                        MROWS, D_EMB, D_EMB, WCOLS, D_EMB);
}